// round 9
// baseline (speedup 1.0000x reference)
#include <cuda_runtime.h>
#include <math.h>
#include <stdint.h>

// ---------------------------------------------------------------------------
// JointMambaFusion: B=4, C=128, H=W=128, D_INNER=256, D_STATE=16, DT_RANK=8
// 4 scans: T = {8192, 4096, 8192, 4096}; token bases c_TB[ib], TOKTOT tokens.
// tf32 tensor-core GEMMs; all GEMM inputs pre-rounded to tf32 at producers.
// ---------------------------------------------------------------------------

#define TOKTOT 98304
#define NCHUNK 32

__constant__ int c_TB[16] = {
    0,     8192,  16384, 24576,
    32768, 36864, 40960, 45056,
    49152, 57344, 65536, 73728,
    81920, 86016, 90112, 94208
};

__device__ float g_X    [4 * 8192 * 128];   // gathered h-scan layout (tf32)
__device__ float g_XZ   [TOKTOT * 512];     // xl | silu(z)
__device__ float g_XS   [TOKTOT * 256];     // u (tf32-rounded)
__device__ float g_XDBL [TOKTOT * 40];
__device__ float g_YT   [TOKTOT * 256];     // y (tf32-rounded)
__device__ float g_OUT  [TOKTOT * 128];
__device__ float g_AB   [2 * 4 * 128 * 64 * 64];
__device__ float g_WTin [4 * 128 * 512];    // (tf32)
__device__ float g_WTxp [4 * 256 * 64];     // (tf32)
__device__ float g_WTout[4 * 256 * 128];    // (tf32)
__device__ float g_CP [16 * NCHUNK * 256 * 16];
__device__ float g_CH [16 * NCHUNK * 256 * 16];
__device__ float g_HI [16 * NCHUNK * 256 * 16];
__device__ int   g_powBad = 0;   // monotone 0->1; both paths correct

__device__ __forceinline__ int scanT(int i) { return (i & 1) ? 4096 : 8192; }

__device__ __forceinline__ float siluf(float x) {
    return __fdividef(x, 1.0f + __expf(-x));
}
__device__ __forceinline__ float softplusf(float x) {
    return (x > 15.0f) ? x : __logf(1.0f + __expf(x));
}
__device__ __forceinline__ uint32_t tf32r(float x) {
    uint32_t u; asm("cvt.rna.tf32.f32 %0, %1;" : "=r"(u) : "f"(x)); return u;
}
__device__ __forceinline__ uint32_t fau(float x) { return __float_as_uint(x); }
__device__ __forceinline__ float tf(float x) { return __uint_as_float(tf32r(x)); }

#define MMA_TF32(C, A, B)                                                     \
    asm volatile("mma.sync.aligned.m16n8k8.row.col.f32.tf32.tf32.f32 "        \
        "{%0,%1,%2,%3},{%4,%5,%6,%7},{%8,%9},{%0,%1,%2,%3};"                  \
        : "+f"((C)[0]), "+f"((C)[1]), "+f"((C)[2]), "+f"((C)[3])              \
        : "r"((A)[0]), "r"((A)[1]), "r"((A)[2]), "r"((A)[3]),                 \
          "r"((B)[0]), "r"((B)[1]))

// row in X_h for (scan i, token t)
__device__ __forceinline__ int rowmap(int i, int t) {
    if (i == 0) return t;
    if (i == 1) return 8191 - 2 * t;
    int l = (i == 2) ? t : (8191 - 2 * t);
    int ww = l >> 7, rr = l & 127;
    return (rr < 64) ? rr * 128 + ww : (rr - 64) * 128 + ww + 64;
}

// ---------------------------------------------------------------------------
// K-1: gather h-scan layout X_h[b][t=hh*128+ww][c], tf32-rounded
// ---------------------------------------------------------------------------
__global__ void k_gather(const float* __restrict__ fa, const float* __restrict__ fb) {
    __shared__ float S[64][129];
    int half = blockIdx.x;
    int hh = blockIdx.y;
    int b = blockIdx.z;
    int tid = threadIdx.x;
    int warp = tid >> 5, lane = tid & 31;
    for (int j = 0; j < 16; j++) {
        int c = warp * 16 + j;
        int planebase = (b * 128 + c) * 16384 + 2 * hh * 128;
        for (int it = 0; it < 2; it++) {
            int wl = it * 32 + lane;
            int ww = half * 64 + wl;
            float v = (ww < 64) ? fa[planebase + 2 * ww]
                                : fb[planebase + 2 * ww - 128];
            S[wl][c] = tf(v);
        }
    }
    __syncthreads();
    int base = (b * 8192 + hh * 128 + half * 64) * 128;
    for (int q = 0; q < 32; q++) {
        int idx = q * 256 + tid;
        int c = idx & 127, row = idx >> 7;
        g_X[base + row * 128 + c] = S[row][c];
    }
}

// ---------------------------------------------------------------------------
// K0a: weight transposes (tf32-rounded)
// ---------------------------------------------------------------------------
__global__ void k_prep_w(const float* __restrict__ inw,
                         const float* __restrict__ xpw,
                         const float* __restrict__ outw) {
    int idx = blockIdx.x * 256 + threadIdx.x;
    if (idx < 4 * 512 * 128) {
        int i = idx / (512 * 128), r = idx % (512 * 128);
        int e = r / 128, c = r % 128;
        g_WTin[(i * 128 + c) * 512 + e] = tf(inw[idx]);
    }
    if (idx < 4 * 256 * 64) {
        int i = idx / (256 * 64), r = idx % (256 * 64);
        int c = r / 64, e = r % 64;
        g_WTxp[idx] = (e < 40) ? tf(xpw[(i * 40 + e) * 256 + c]) : 0.0f;
    }
    if (idx < 4 * 256 * 128) {
        int i = idx / (256 * 128), r = idx % (256 * 128);
        int c = r / 128, o = r % 128;
        g_WTout[idx] = tf(outw[(i * 128 + o) * 256 + c]);
    }
}

// K0b: A_log structure check
__global__ void k_prep_chk(const float* __restrict__ alog) {
    int idx = blockIdx.x * 256 + threadIdx.x;
    if (idx < 4 * 256 * 16) {
        int s = idx & 15;
        int dI = idx >> 4;
        float As = -__expf(alog[dI * 16 + s]);
        float A0 = -__expf(alog[dI * 16]);
        float ratio = As / A0;
        if (fabsf(ratio - (float)(s + 1)) > 1e-5f * (float)(s + 1))
            atomicOr(&g_powBad, 1);
    }
}

// ---------------------------------------------------------------------------
// K1: in_proj tf32 GEMM.  block tile 128x128, warp tile 32x64, K=128.
// z half (cols>=256 -> nt>=2) silu'd in epilogue.
// ---------------------------------------------------------------------------
__global__ void __launch_bounds__(256, 2) k_gemm_in() {
    __shared__ __align__(16) float As[128][36];
    __shared__ __align__(16) float Bs[32][136];
    int nt = blockIdx.x;                 // 0..3 (128-col tile of 512)
    int tt = blockIdx.y;
    int ib = blockIdx.z;
    int i = ib >> 2, b = ib & 3;
    int T = scanT(i);
    if (tt * 128 >= T) return;
    int t0 = tt * 128;
    int tid = threadIdx.x;
    int warp = tid >> 5, lane = tid & 31;
    int wm = warp & 3, wn = warp >> 2;
    int lg = lane >> 2, lt = lane & 3;
    float c[2][8][4] = {};
    for (int kc = 0; kc < 4; kc++) {
        for (int p = 0; p < 4; p++) {
            int q = p * 256 + tid;
            int kk4 = q & 7, m = q >> 3;
            int r = rowmap(i, t0 + m);
            *(float4*)&As[m][kk4 * 4] =
                *(const float4*)&g_X[(b * 8192 + r) * 128 + kc * 32 + kk4 * 4];
        }
        for (int p = 0; p < 4; p++) {
            int q = p * 256 + tid;
            int n4 = q & 31, kk = q >> 5;
            *(float4*)&Bs[kk][n4 * 4] =
                *(const float4*)&g_WTin[(i * 128 + kc * 32 + kk) * 512 + nt * 128 + n4 * 4];
        }
        __syncthreads();
#pragma unroll
        for (int k8 = 0; k8 < 4; k8++) {
            int kq = k8 * 8 + lt;
            uint32_t a[2][4];
#pragma unroll
            for (int mt = 0; mt < 2; mt++) {
                int mr = wm * 32 + mt * 16 + lg;
                a[mt][0] = fau(As[mr][kq]);     a[mt][1] = fau(As[mr + 8][kq]);
                a[mt][2] = fau(As[mr][kq + 4]); a[mt][3] = fau(As[mr + 8][kq + 4]);
            }
            uint32_t bb[8][2];
#pragma unroll
            for (int n4 = 0; n4 < 8; n4++) {
                int nb = wn * 64 + n4 * 8 + lg;
                bb[n4][0] = fau(Bs[kq][nb]);
                bb[n4][1] = fau(Bs[kq + 4][nb]);
            }
#pragma unroll
            for (int mt = 0; mt < 2; mt++)
#pragma unroll
                for (int n4 = 0; n4 < 8; n4++)
                    MMA_TF32(c[mt][n4], a[mt], bb[n4]);
        }
        __syncthreads();
    }
    int SB = c_TB[ib];
    bool isz = (nt >= 2);
#pragma unroll
    for (int mt = 0; mt < 2; mt++)
#pragma unroll
        for (int n4 = 0; n4 < 8; n4++) {
            int row = t0 + wm * 32 + mt * 16 + lg;
            int col = nt * 128 + wn * 64 + n4 * 8 + 2 * lt;
            float2 v0 = make_float2(c[mt][n4][0], c[mt][n4][1]);
            float2 v1 = make_float2(c[mt][n4][2], c[mt][n4][3]);
            if (isz) {
                v0.x = siluf(v0.x); v0.y = siluf(v0.y);
                v1.x = siluf(v1.x); v1.y = siluf(v1.y);
            }
            *(float2*)&g_XZ[(SB + row) * 512 + col]     = v0;
            *(float2*)&g_XZ[(SB + row + 8) * 512 + col] = v1;
        }
}

// ---------------------------------------------------------------------------
// K2: causal conv(4)+silu -> XS (tf32-rounded) token-major.
// ---------------------------------------------------------------------------
__global__ void k_conv(const float* __restrict__ cw, const float* __restrict__ cb) {
    int tc = blockIdx.x, ib = blockIdx.y;
    int i = ib >> 2;
    int T = scanT(i);
    if (tc * 64 >= T) return;
    int d = threadIdx.x;
    int SB = c_TB[ib];
    const float* w = &cw[(i * 256 + d) * 4];
    float w0 = w[0], w1 = w[1], w2 = w[2], w3 = w[3];
    float bias = cb[i * 256 + d];
    const float* px = &g_XZ[SB * 512 + d];
    float* pxs = &g_XS[SB * 256 + d];
    int t0 = tc * 64;
    float xm1 = (t0 >= 1) ? px[(t0 - 1) * 512] : 0.0f;
    float xm2 = (t0 >= 2) ? px[(t0 - 2) * 512] : 0.0f;
    float xm3 = (t0 >= 3) ? px[(t0 - 3) * 512] : 0.0f;
    for (int q4 = 0; q4 < 16; q4++) {
        float xv[4];
#pragma unroll
        for (int j = 0; j < 4; j++) xv[j] = px[(t0 + q4 * 4 + j) * 512];
#pragma unroll
        for (int j = 0; j < 4; j++) {
            float x = xv[j];
            float acc = fmaf(x, w3, fmaf(xm1, w2, fmaf(xm2, w1, fmaf(xm3, w0, bias))));
            pxs[(t0 + q4 * 4 + j) * 256] = tf(siluf(acc));
            xm3 = xm2; xm2 = xm1; xm1 = x;
        }
    }
}

// ---------------------------------------------------------------------------
// K3: x_proj tf32 GEMM.  tile 128x64, K=256.  valid cols < 40.
// ---------------------------------------------------------------------------
__global__ void k_gemm_xp() {
    __shared__ __align__(16) float As[128][36];
    __shared__ __align__(16) float Bs[32][72];
    int tt = blockIdx.y;
    int ib = blockIdx.z;
    int i = ib >> 2;
    int T = scanT(i);
    if (tt * 128 >= T) return;
    int t0 = tt * 128;
    int SB = c_TB[ib];
    int tid = threadIdx.x;
    int warp = tid >> 5, lane = tid & 31;
    int wm = warp & 3, wn = warp >> 2;
    int lg = lane >> 2, lt = lane & 3;
    float c[2][4][4] = {};
    for (int kc = 0; kc < 8; kc++) {
        for (int p = 0; p < 4; p++) {
            int q = p * 256 + tid;
            int kk4 = q & 7, m = q >> 3;
            *(float4*)&As[m][kk4 * 4] =
                *(const float4*)&g_XS[(SB + t0 + m) * 256 + kc * 32 + kk4 * 4];
        }
        for (int p = 0; p < 2; p++) {
            int q = p * 256 + tid;
            int n4 = q & 15, kk = q >> 4;
            *(float4*)&Bs[kk][n4 * 4] =
                *(const float4*)&g_WTxp[(i * 256 + kc * 32 + kk) * 64 + n4 * 4];
        }
        __syncthreads();
#pragma unroll
        for (int k8 = 0; k8 < 4; k8++) {
            int kq = k8 * 8 + lt;
            uint32_t a[2][4];
#pragma unroll
            for (int mt = 0; mt < 2; mt++) {
                int mr = wm * 32 + mt * 16 + lg;
                a[mt][0] = fau(As[mr][kq]);     a[mt][1] = fau(As[mr + 8][kq]);
                a[mt][2] = fau(As[mr][kq + 4]); a[mt][3] = fau(As[mr + 8][kq + 4]);
            }
            uint32_t bb[4][2];
#pragma unroll
            for (int n4 = 0; n4 < 4; n4++) {
                int nb = wn * 32 + n4 * 8 + lg;
                bb[n4][0] = fau(Bs[kq][nb]);
                bb[n4][1] = fau(Bs[kq + 4][nb]);
            }
#pragma unroll
            for (int mt = 0; mt < 2; mt++)
#pragma unroll
                for (int n4 = 0; n4 < 4; n4++)
                    MMA_TF32(c[mt][n4], a[mt], bb[n4]);
        }
        __syncthreads();
    }
#pragma unroll
    for (int mt = 0; mt < 2; mt++)
#pragma unroll
        for (int n4 = 0; n4 < 4; n4++) {
            int row = t0 + wm * 32 + mt * 16 + lg;
            int col = wn * 32 + n4 * 8 + 2 * lt;
            if (col < 40) {
                *(float2*)&g_XDBL[(SB + row) * 40 + col]     = make_float2(c[mt][n4][0], c[mt][n4][1]);
                *(float2*)&g_XDBL[(SB + row + 8) * 40 + col] = make_float2(c[mt][n4][2], c[mt][n4][3]);
            }
        }
}

// ---------------------------------------------------------------------------
// K5a: chunk-local scan (delta fused inline). thread=d.
// ---------------------------------------------------------------------------
__global__ void k_scan1(const float* __restrict__ alog,
                        const float* __restrict__ dtw, const float* __restrict__ dtb) {
    int c = blockIdx.x, ib = blockIdx.y;
    int i = ib >> 2;
    int T = scanT(i);
    int LC = T / NCHUNK;
    int d = threadIdx.x;
    int SB = c_TB[ib];
    bool pw = (g_powBad == 0);
    float A0 = -__expf(alog[(i * 256 + d) * 16]);
    float4 dw0 = *(const float4*)&dtw[(i * 256 + d) * 8];
    float4 dw1 = *(const float4*)&dtw[(i * 256 + d) * 8 + 4];
    float dbias = dtb[i * 256 + d];
    const float* pU = &g_XS[SB * 256 + d];
    const float* pBC = &g_XDBL[SB * 40];
    float h[16];
#pragma unroll
    for (int s = 0; s < 16; s++) h[s] = 0.0f;
    float dsum = 0.0f;
    int t0 = c * LC;
    if (pw) {
#pragma unroll 2
        for (int t = t0; t < t0 + LC; t++) {
            const float4* r = (const float4*)&pBC[t * 40];
            float4 a0 = r[0], a1 = r[1];
            float pre = dbias;
            pre = fmaf(a0.x, dw0.x, pre); pre = fmaf(a0.y, dw0.y, pre);
            pre = fmaf(a0.z, dw0.z, pre); pre = fmaf(a0.w, dw0.w, pre);
            pre = fmaf(a1.x, dw1.x, pre); pre = fmaf(a1.y, dw1.y, pre);
            pre = fmaf(a1.z, dw1.z, pre); pre = fmaf(a1.w, dw1.w, pre);
            float dv = softplusf(pre);
            float du = dv * pU[t * 256];
            dsum += dv;
            float q = __expf(dv * A0);
            float4 B0 = r[2], B1 = r[3], B2 = r[4], B3 = r[5];
            float ap = q;
            h[0]  = fmaf(ap, h[0],  du * B0.x); ap *= q;
            h[1]  = fmaf(ap, h[1],  du * B0.y); ap *= q;
            h[2]  = fmaf(ap, h[2],  du * B0.z); ap *= q;
            h[3]  = fmaf(ap, h[3],  du * B0.w); ap *= q;
            h[4]  = fmaf(ap, h[4],  du * B1.x); ap *= q;
            h[5]  = fmaf(ap, h[5],  du * B1.y); ap *= q;
            h[6]  = fmaf(ap, h[6],  du * B1.z); ap *= q;
            h[7]  = fmaf(ap, h[7],  du * B1.w); ap *= q;
            h[8]  = fmaf(ap, h[8],  du * B2.x); ap *= q;
            h[9]  = fmaf(ap, h[9],  du * B2.y); ap *= q;
            h[10] = fmaf(ap, h[10], du * B2.z); ap *= q;
            h[11] = fmaf(ap, h[11], du * B2.w); ap *= q;
            h[12] = fmaf(ap, h[12], du * B3.x); ap *= q;
            h[13] = fmaf(ap, h[13], du * B3.y); ap *= q;
            h[14] = fmaf(ap, h[14], du * B3.z); ap *= q;
            h[15] = fmaf(ap, h[15], du * B3.w);
        }
    } else {
        float As[16];
#pragma unroll
        for (int s = 0; s < 16; s++) As[s] = -__expf(alog[(i * 256 + d) * 16 + s]);
        for (int t = t0; t < t0 + LC; t++) {
            const float4* r = (const float4*)&pBC[t * 40];
            float4 a0 = r[0], a1 = r[1];
            float pre = dbias;
            pre = fmaf(a0.x, dw0.x, pre); pre = fmaf(a0.y, dw0.y, pre);
            pre = fmaf(a0.z, dw0.z, pre); pre = fmaf(a0.w, dw0.w, pre);
            pre = fmaf(a1.x, dw1.x, pre); pre = fmaf(a1.y, dw1.y, pre);
            pre = fmaf(a1.z, dw1.z, pre); pre = fmaf(a1.w, dw1.w, pre);
            float dv = softplusf(pre);
            float du = dv * pU[t * 256];
            dsum += dv;
            const float* Bp = &pBC[t * 40 + 8];
#pragma unroll
            for (int s = 0; s < 16; s++) {
                float a = __expf(dv * As[s]);
                h[s] = fmaf(a, h[s], du * Bp[s]);
            }
        }
    }
    int base = ((ib * NCHUNK + c) * 256 + d) * 16;
#pragma unroll
    for (int s = 0; s < 16; s++) {
        float Ascale = pw ? (A0 * (float)(s + 1))
                          : (-__expf(alog[(i * 256 + d) * 16 + s]));
        g_CP[base + s] = __expf(Ascale * dsum);
        g_CH[base + s] = h[s];
    }
}

// ---------------------------------------------------------------------------
// K5b: prefix over chunks
// ---------------------------------------------------------------------------
__global__ void k_scan2() {
    int g = blockIdx.x * 256 + threadIdx.x;
    int ib = g >> 12;
    int rem = g & 4095;
    float hi = 0.0f;
    for (int c = 0; c < NCHUNK; c++) {
        int idx = ib * (NCHUNK * 4096) + c * 4096 + rem;
        g_HI[idx] = hi;
        hi = fmaf(g_CP[idx], hi, g_CH[idx]);
    }
}

// ---------------------------------------------------------------------------
// K5c: chunk recompute with true h_init; y -> YT (tf32-rounded) token-major.
// ---------------------------------------------------------------------------
__global__ void k_scan3(const float* __restrict__ alog, const float* __restrict__ Dv,
                        const float* __restrict__ dtw, const float* __restrict__ dtb) {
    int c = blockIdx.x, ib = blockIdx.y;
    int i = ib >> 2;
    int T = scanT(i);
    int LC = T / NCHUNK;
    int d = threadIdx.x;
    int SB = c_TB[ib];
    bool pw = (g_powBad == 0);
    float A0 = -__expf(alog[(i * 256 + d) * 16]);
    float Dreg = Dv[i * 256 + d];
    float4 dw0 = *(const float4*)&dtw[(i * 256 + d) * 8];
    float4 dw1 = *(const float4*)&dtw[(i * 256 + d) * 8 + 4];
    float dbias = dtb[i * 256 + d];
    const float* pU = &g_XS[SB * 256 + d];
    const float* pZ = &g_XZ[SB * 512 + 256 + d];
    const float* pBC = &g_XDBL[SB * 40];
    float* pY = &g_YT[SB * 256 + d];
    float h[16];
    {
        int base = ((ib * NCHUNK + c) * 256 + d) * 16;
#pragma unroll
        for (int s = 0; s < 16; s++) h[s] = g_HI[base + s];
    }
    int t0 = c * LC;
    if (pw) {
#pragma unroll 2
        for (int t = t0; t < t0 + LC; t++) {
            const float4* r = (const float4*)&pBC[t * 40];
            float4 a0 = r[0], a1 = r[1];
            float pre = dbias;
            pre = fmaf(a0.x, dw0.x, pre); pre = fmaf(a0.y, dw0.y, pre);
            pre = fmaf(a0.z, dw0.z, pre); pre = fmaf(a0.w, dw0.w, pre);
            pre = fmaf(a1.x, dw1.x, pre); pre = fmaf(a1.y, dw1.y, pre);
            pre = fmaf(a1.z, dw1.z, pre); pre = fmaf(a1.w, dw1.w, pre);
            float dv = softplusf(pre);
            float u = pU[t * 256];
            float du = dv * u;
            float q = __expf(dv * A0);
            float4 B0 = r[2], B1 = r[3], B2 = r[4], B3 = r[5];
            float4 C0 = r[6], C1 = r[7], C2 = r[8], C3 = r[9];
            float ys = 0.0f;
            float ap = q;
            h[0]  = fmaf(ap, h[0],  du * B0.x); ys = fmaf(h[0],  C0.x, ys); ap *= q;
            h[1]  = fmaf(ap, h[1],  du * B0.y); ys = fmaf(h[1],  C0.y, ys); ap *= q;
            h[2]  = fmaf(ap, h[2],  du * B0.z); ys = fmaf(h[2],  C0.z, ys); ap *= q;
            h[3]  = fmaf(ap, h[3],  du * B0.w); ys = fmaf(h[3],  C0.w, ys); ap *= q;
            h[4]  = fmaf(ap, h[4],  du * B1.x); ys = fmaf(h[4],  C1.x, ys); ap *= q;
            h[5]  = fmaf(ap, h[5],  du * B1.y); ys = fmaf(h[5],  C1.y, ys); ap *= q;
            h[6]  = fmaf(ap, h[6],  du * B1.z); ys = fmaf(h[6],  C1.z, ys); ap *= q;
            h[7]  = fmaf(ap, h[7],  du * B1.w); ys = fmaf(h[7],  C1.w, ys); ap *= q;
            h[8]  = fmaf(ap, h[8],  du * B2.x); ys = fmaf(h[8],  C2.x, ys); ap *= q;
            h[9]  = fmaf(ap, h[9],  du * B2.y); ys = fmaf(h[9],  C2.y, ys); ap *= q;
            h[10] = fmaf(ap, h[10], du * B2.z); ys = fmaf(h[10], C2.z, ys); ap *= q;
            h[11] = fmaf(ap, h[11], du * B2.w); ys = fmaf(h[11], C2.w, ys); ap *= q;
            h[12] = fmaf(ap, h[12], du * B3.x); ys = fmaf(h[12], C3.x, ys); ap *= q;
            h[13] = fmaf(ap, h[13], du * B3.y); ys = fmaf(h[13], C3.y, ys); ap *= q;
            h[14] = fmaf(ap, h[14], du * B3.z); ys = fmaf(h[14], C3.z, ys); ap *= q;
            h[15] = fmaf(ap, h[15], du * B3.w); ys = fmaf(h[15], C3.w, ys);
            float z = pZ[t * 512];
            pY[t * 256] = tf(fmaf(u, Dreg, ys) * z);
        }
    } else {
        float As[16];
#pragma unroll
        for (int s = 0; s < 16; s++) As[s] = -__expf(alog[(i * 256 + d) * 16 + s]);
        for (int t = t0; t < t0 + LC; t++) {
            const float4* r = (const float4*)&pBC[t * 40];
            float4 a0 = r[0], a1 = r[1];
            float pre = dbias;
            pre = fmaf(a0.x, dw0.x, pre); pre = fmaf(a0.y, dw0.y, pre);
            pre = fmaf(a0.z, dw0.z, pre); pre = fmaf(a0.w, dw0.w, pre);
            pre = fmaf(a1.x, dw1.x, pre); pre = fmaf(a1.y, dw1.y, pre);
            pre = fmaf(a1.z, dw1.z, pre); pre = fmaf(a1.w, dw1.w, pre);
            float dv = softplusf(pre);
            float u = pU[t * 256];
            float du = dv * u;
            const float* Bp = &pBC[t * 40 + 8];
            float ys = 0.0f;
#pragma unroll
            for (int s = 0; s < 16; s++) {
                float a = __expf(dv * As[s]);
                h[s] = fmaf(a, h[s], du * Bp[s]);
                ys = fmaf(h[s], Bp[16 + s], ys);
            }
            float z = pZ[t * 512];
            pY[t * 256] = tf(fmaf(u, Dreg, ys) * z);
        }
    }
}

// ---------------------------------------------------------------------------
// K6: out_proj tf32 GEMM.  block tile 128x128 (full N), warp tile 32x64, K=256.
// ---------------------------------------------------------------------------
__global__ void __launch_bounds__(256, 2) k_gemm_out() {
    __shared__ __align__(16) float As[128][36];
    __shared__ __align__(16) float Bs[32][136];
    int tt = blockIdx.y;
    int ib = blockIdx.z;
    int i = ib >> 2;
    int T = scanT(i);
    if (tt * 128 >= T) return;
    int t0 = tt * 128;
    int SB = c_TB[ib];
    int tid = threadIdx.x;
    int warp = tid >> 5, lane = tid & 31;
    int wm = warp & 3, wn = warp >> 2;
    int lg = lane >> 2, lt = lane & 3;
    float c[2][8][4] = {};
    for (int kc = 0; kc < 8; kc++) {
        for (int p = 0; p < 4; p++) {
            int q = p * 256 + tid;
            int kk4 = q & 7, m = q >> 3;
            *(float4*)&As[m][kk4 * 4] =
                *(const float4*)&g_YT[(SB + t0 + m) * 256 + kc * 32 + kk4 * 4];
        }
        for (int p = 0; p < 4; p++) {
            int q = p * 256 + tid;
            int n4 = q & 31, kk = q >> 5;
            *(float4*)&Bs[kk][n4 * 4] =
                *(const float4*)&g_WTout[(i * 256 + kc * 32 + kk) * 128 + n4 * 4];
        }
        __syncthreads();
#pragma unroll
        for (int k8 = 0; k8 < 4; k8++) {
            int kq = k8 * 8 + lt;
            uint32_t a[2][4];
#pragma unroll
            for (int mt = 0; mt < 2; mt++) {
                int mr = wm * 32 + mt * 16 + lg;
                a[mt][0] = fau(As[mr][kq]);     a[mt][1] = fau(As[mr + 8][kq]);
                a[mt][2] = fau(As[mr][kq + 4]); a[mt][3] = fau(As[mr + 8][kq + 4]);
            }
            uint32_t bb[8][2];
#pragma unroll
            for (int n4 = 0; n4 < 8; n4++) {
                int nb = wn * 64 + n4 * 8 + lg;
                bb[n4][0] = fau(Bs[kq][nb]);
                bb[n4][1] = fau(Bs[kq + 4][nb]);
            }
#pragma unroll
            for (int mt = 0; mt < 2; mt++)
#pragma unroll
                for (int n4 = 0; n4 < 8; n4++)
                    MMA_TF32(c[mt][n4], a[mt], bb[n4]);
        }
        __syncthreads();
    }
#pragma unroll
    for (int mt = 0; mt < 2; mt++)
#pragma unroll
        for (int n4 = 0; n4 < 8; n4++) {
            int row = t0 + wm * 32 + mt * 16 + lg;
            int col = wn * 64 + n4 * 8 + 2 * lt;
            *(float2*)&g_OUT[(SB + row) * 128 + col]     = make_float2(c[mt][n4][0], c[mt][n4][1]);
            *(float2*)&g_OUT[(SB + row + 8) * 128 + col] = make_float2(c[mt][n4][2], c[mt][n4][3]);
        }
}

// interp of backward-scan output
__device__ __forceinline__ float interp_flip(int i, int b, int l, int c) {
    float pos = 0.5f * (float)(8191 - l) - 0.25f;
    pos = fminf(fmaxf(pos, 0.0f), 4095.0f);
    int lo = (int)floorf(pos);
    int hi = min(lo + 1, 4095);
    float w = pos - (float)lo;
    const float* ob = &g_OUT[c_TB[i * 4 + b] * 128 + c];
    return ob[lo * 128] * (1.0f - w) + ob[hi * 128] * w;
}

// ---------------------------------------------------------------------------
// K7: merge 4 scan outputs -> a,b maps [2][B][C][64][64]
// ---------------------------------------------------------------------------
__global__ void k_merge() {
    __shared__ float S[64][129];
    int irow = blockIdx.x;
    int b = blockIdx.y;
    int tid = threadIdx.x;
    for (int half = 0; half < 2; half++) {
        for (int p = 0; p < 32; p++) {
            int idx = p * 256 + tid;
            int c = idx & 127, j = idx >> 7;
            int l  = irow * 128 + j + (half ? 64 : 0);
            int l2 = j * 128 + irow + (half ? 64 : 0);
            float v = g_OUT[(c_TB[b] + l) * 128 + c];
            v += interp_flip(1, b, l, c);
            v += g_OUT[(c_TB[8 + b] + l2) * 128 + c];
            v += interp_flip(3, b, l2, c);
            S[j][c] = v;
        }
        __syncthreads();
        for (int p = 0; p < 32; p++) {
            int idx = p * 256 + tid;
            int j = idx & 63, c = idx >> 6;
            g_AB[((half * 4 + b) * 128 + c) * 4096 + irow * 64 + j] = S[j][c];
        }
        __syncthreads();
    }
}

// ---------------------------------------------------------------------------
// K8: bilinear 64->128 upsample + residuals
// ---------------------------------------------------------------------------
__global__ void k_final(const float* __restrict__ fa, const float* __restrict__ fb,
                        float* __restrict__ out) {
    int idx = blockIdx.x * 256 + threadIdx.x;
    int w = idx & 127, hh = (idx >> 7) & 127, c = (idx >> 14) & 127, b = idx >> 21;
    float ph = fminf(fmaxf(0.5f * hh - 0.25f, 0.0f), 63.0f);
    int h0 = (int)floorf(ph); int h1 = min(h0 + 1, 63); float wh = ph - (float)h0;
    float pw = fminf(fmaxf(0.5f * w - 0.25f, 0.0f), 63.0f);
    int w0 = (int)floorf(pw); int w1 = min(w0 + 1, 63); float ww = pw - (float)w0;
    const float* Aa = &g_AB[((0 * 4 + b) * 128 + c) * 4096];
    const float* Bb = &g_AB[((1 * 4 + b) * 128 + c) * 4096];
    float av = (Aa[h0 * 64 + w0] * (1.0f - ww) + Aa[h0 * 64 + w1] * ww) * (1.0f - wh)
             + (Aa[h1 * 64 + w0] * (1.0f - ww) + Aa[h1 * 64 + w1] * ww) * wh;
    float bv = (Bb[h0 * 64 + w0] * (1.0f - ww) + Bb[h0 * 64 + w1] * ww) * (1.0f - wh)
             + (Bb[h1 * 64 + w0] * (1.0f - ww) + Bb[h1 * 64 + w1] * ww) * wh;
    out[idx] = av + bv + fa[idx] + fb[idx];
}

// ---------------------------------------------------------------------------
extern "C" void kernel_launch(void* const* d_in, const int* in_sizes, int n_in,
                              void* d_out, int out_size) {
    (void)in_sizes; (void)n_in; (void)out_size;
    const float* fa   = (const float*)d_in[0];
    const float* fb   = (const float*)d_in[1];
    const float* inw  = (const float*)d_in[2];
    const float* cw   = (const float*)d_in[3];
    const float* cb   = (const float*)d_in[4];
    const float* xpw  = (const float*)d_in[5];
    const float* dtw  = (const float*)d_in[6];
    const float* dtb  = (const float*)d_in[7];
    const float* alog = (const float*)d_in[8];
    const float* Dv   = (const float*)d_in[9];
    const float* outw = (const float*)d_in[10];
    float* out = (float*)d_out;

    k_gather<<<dim3(2, 64, 4), 256>>>(fa, fb);
    k_prep_w<<<1024, 256>>>(inw, xpw, outw);
    k_prep_chk<<<64, 256>>>(alog);
    k_gemm_in<<<dim3(4, 64, 16), 256>>>();
    k_conv<<<dim3(128, 16), 256>>>(cw, cb);
    k_gemm_xp<<<dim3(1, 64, 16), 256>>>();
    k_scan1<<<dim3(NCHUNK, 16), 256>>>(alog, dtw, dtb);
    k_scan2<<<256, 256>>>();
    k_scan3<<<dim3(NCHUNK, 16), 256>>>(alog, Dv, dtw, dtb);
    k_gemm_out<<<dim3(1, 64, 16), 256>>>();
    k_merge<<<dim3(64, 4), 256>>>();
    k_final<<<32768, 256>>>(fa, fb, out);
}

// round 10
// speedup vs baseline: 1.0736x; 1.0736x over previous
#include <cuda_runtime.h>
#include <math.h>
#include <stdint.h>

// ---------------------------------------------------------------------------
// JointMambaFusion: B=4, C=128, H=W=128, D_INNER=256, D_STATE=16, DT_RANK=8
// 4 scans: T = {8192, 4096, 8192, 4096}; token bases c_TB[ib], TOKTOT tokens.
// tf32 tensor-core GEMMs with 2-stage cp.async pipelines (dynamic smem).
// All GEMM inputs pre-rounded to tf32 at producers.
// ---------------------------------------------------------------------------

#define TOKTOT 98304
#define NCHUNK 32

__constant__ int c_TB[16] = {
    0,     8192,  16384, 24576,
    32768, 36864, 40960, 45056,
    49152, 57344, 65536, 73728,
    81920, 86016, 90112, 94208
};

__device__ float g_X    [4 * 8192 * 128];   // gathered h-scan layout (tf32)
__device__ float g_XZ   [TOKTOT * 512];     // xl | silu(z)
__device__ float g_XS   [TOKTOT * 256];     // u (tf32-rounded)
__device__ float g_XDBL [TOKTOT * 40];
__device__ float g_YT   [TOKTOT * 256];     // y (tf32-rounded)
__device__ float g_OUT  [TOKTOT * 128];
__device__ float g_AB   [2 * 4 * 128 * 64 * 64];
__device__ float g_WTin [4 * 128 * 512];    // (tf32)
__device__ float g_WTxp [4 * 256 * 64];     // (tf32)
__device__ float g_WTout[4 * 256 * 128];    // (tf32)
__device__ float g_CP [16 * NCHUNK * 256 * 16];
__device__ float g_CH [16 * NCHUNK * 256 * 16];
__device__ float g_HI [16 * NCHUNK * 256 * 16];
__device__ int   g_powBad = 0;

__device__ __forceinline__ int scanT(int i) { return (i & 1) ? 4096 : 8192; }

__device__ __forceinline__ float siluf(float x) {
    return __fdividef(x, 1.0f + __expf(-x));
}
__device__ __forceinline__ float softplusf(float x) {
    return (x > 15.0f) ? x : __logf(1.0f + __expf(x));
}
__device__ __forceinline__ uint32_t tf32r(float x) {
    uint32_t u; asm("cvt.rna.tf32.f32 %0, %1;" : "=r"(u) : "f"(x)); return u;
}
__device__ __forceinline__ uint32_t fau(float x) { return __float_as_uint(x); }
__device__ __forceinline__ float tf(float x) { return __uint_as_float(tf32r(x)); }

__device__ __forceinline__ void cpa16(void* dst_smem, const float* src) {
    uint32_t dst = (uint32_t)__cvta_generic_to_shared(dst_smem);
    asm volatile("cp.async.cg.shared.global [%0], [%1], 16;" :: "r"(dst), "l"(src));
}
#define CP_COMMIT() asm volatile("cp.async.commit_group;" ::: "memory")
#define CP_WAIT1()  asm volatile("cp.async.wait_group 1;" ::: "memory")
#define CP_WAIT0()  asm volatile("cp.async.wait_group 0;" ::: "memory")

#define MMA_TF32(C, A, B)                                                     \
    asm volatile("mma.sync.aligned.m16n8k8.row.col.f32.tf32.tf32.f32 "        \
        "{%0,%1,%2,%3},{%4,%5,%6,%7},{%8,%9},{%0,%1,%2,%3};"                  \
        : "+f"((C)[0]), "+f"((C)[1]), "+f"((C)[2]), "+f"((C)[3])              \
        : "r"((A)[0]), "r"((A)[1]), "r"((A)[2]), "r"((A)[3]),                 \
          "r"((B)[0]), "r"((B)[1]))

// row in X_h for (scan i, token t)
__device__ __forceinline__ int rowmap(int i, int t) {
    if (i == 0) return t;
    if (i == 1) return 8191 - 2 * t;
    int l = (i == 2) ? t : (8191 - 2 * t);
    int ww = l >> 7, rr = l & 127;
    return (rr < 64) ? rr * 128 + ww : (rr - 64) * 128 + ww + 64;
}

// ---------------------------------------------------------------------------
// K-1: gather h-scan layout X_h[b][t=hh*128+ww][c], tf32-rounded
// ---------------------------------------------------------------------------
__global__ void k_gather(const float* __restrict__ fa, const float* __restrict__ fb) {
    __shared__ float S[64][129];
    int half = blockIdx.x;
    int hh = blockIdx.y;
    int b = blockIdx.z;
    int tid = threadIdx.x;
    int warp = tid >> 5, lane = tid & 31;
    for (int j = 0; j < 16; j++) {
        int c = warp * 16 + j;
        int planebase = (b * 128 + c) * 16384 + 2 * hh * 128;
        for (int it = 0; it < 2; it++) {
            int wl = it * 32 + lane;
            int ww = half * 64 + wl;
            float v = (ww < 64) ? fa[planebase + 2 * ww]
                                : fb[planebase + 2 * ww - 128];
            S[wl][c] = tf(v);
        }
    }
    __syncthreads();
    int base = (b * 8192 + hh * 128 + half * 64) * 128;
    for (int q = 0; q < 32; q++) {
        int idx = q * 256 + tid;
        int c = idx & 127, row = idx >> 7;
        g_X[base + row * 128 + c] = S[row][c];
    }
}

// ---------------------------------------------------------------------------
// K0a: weight transposes (tf32-rounded)
// ---------------------------------------------------------------------------
__global__ void k_prep_w(const float* __restrict__ inw,
                         const float* __restrict__ xpw,
                         const float* __restrict__ outw) {
    int idx = blockIdx.x * 256 + threadIdx.x;
    if (idx < 4 * 512 * 128) {
        int i = idx / (512 * 128), r = idx % (512 * 128);
        int e = r / 128, c = r % 128;
        g_WTin[(i * 128 + c) * 512 + e] = tf(inw[idx]);
    }
    if (idx < 4 * 256 * 64) {
        int i = idx / (256 * 64), r = idx % (256 * 64);
        int c = r / 64, e = r % 64;
        g_WTxp[idx] = (e < 40) ? tf(xpw[(i * 40 + e) * 256 + c]) : 0.0f;
    }
    if (idx < 4 * 256 * 128) {
        int i = idx / (256 * 128), r = idx % (256 * 128);
        int c = r / 128, o = r % 128;
        g_WTout[idx] = tf(outw[(i * 128 + o) * 256 + c]);
    }
}

// K0b: A_log structure check
__global__ void k_prep_chk(const float* __restrict__ alog) {
    int idx = blockIdx.x * 256 + threadIdx.x;
    if (idx < 4 * 256 * 16) {
        int s = idx & 15;
        int dI = idx >> 4;
        float As = -__expf(alog[dI * 16 + s]);
        float A0 = -__expf(alog[dI * 16]);
        float ratio = As / A0;
        if (fabsf(ratio - (float)(s + 1)) > 1e-5f * (float)(s + 1))
            atomicOr(&g_powBad, 1);
    }
}

// ---------------------------------------------------------------------------
// K1: in_proj tf32 GEMM.  128x128 tile, K=128, 2-stage cp.async pipeline.
// z half (nt>=2) silu'd in epilogue.
// ---------------------------------------------------------------------------
#define IN_ASZ (128 * 36)
#define IN_BSZ (32 * 136)
__global__ void __launch_bounds__(256, 2) k_gemm_in() {
    extern __shared__ float dsm[];
    float* Asm = dsm;                 // [2][128][36]
    float* Bsm = dsm + 2 * IN_ASZ;    // [2][32][136]
    int nt = blockIdx.x;              // 0..3
    int tt = blockIdx.y;
    int ib = blockIdx.z;
    int i = ib >> 2, b = ib & 3;
    int T = scanT(i);
    if (tt * 128 >= T) return;
    int t0 = tt * 128;
    int tid = threadIdx.x;
    int warp = tid >> 5, lane = tid & 31;
    int wm = warp & 3, wn = warp >> 2;
    int lg = lane >> 2, lt = lane & 3;

    auto load_stage = [&](int st, int kc) {
#pragma unroll
        for (int p = 0; p < 4; p++) {
            int q = p * 256 + tid;
            int kk4 = q & 7, m = q >> 3;
            int r = rowmap(i, t0 + m);
            cpa16(&Asm[st * IN_ASZ + m * 36 + kk4 * 4],
                  &g_X[(b * 8192 + r) * 128 + kc * 32 + kk4 * 4]);
        }
#pragma unroll
        for (int p = 0; p < 4; p++) {
            int q = p * 256 + tid;
            int n4 = q & 31, kk = q >> 5;
            cpa16(&Bsm[st * IN_BSZ + kk * 136 + n4 * 4],
                  &g_WTin[(i * 128 + kc * 32 + kk) * 512 + nt * 128 + n4 * 4]);
        }
    };

    float c[2][8][4] = {};
    load_stage(0, 0); CP_COMMIT();
    for (int kc = 0; kc < 4; kc++) {
        if (kc + 1 < 4) { load_stage((kc + 1) & 1, kc + 1); CP_COMMIT(); CP_WAIT1(); }
        else CP_WAIT0();
        __syncthreads();
        const float* Ab = &Asm[(kc & 1) * IN_ASZ];
        const float* Bb = &Bsm[(kc & 1) * IN_BSZ];
#pragma unroll
        for (int k8 = 0; k8 < 4; k8++) {
            int kq = k8 * 8 + lt;
            uint32_t a[2][4];
#pragma unroll
            for (int mt = 0; mt < 2; mt++) {
                int mr = wm * 32 + mt * 16 + lg;
                a[mt][0] = fau(Ab[mr * 36 + kq]);         a[mt][1] = fau(Ab[(mr + 8) * 36 + kq]);
                a[mt][2] = fau(Ab[mr * 36 + kq + 4]);     a[mt][3] = fau(Ab[(mr + 8) * 36 + kq + 4]);
            }
            uint32_t bb[8][2];
#pragma unroll
            for (int n4 = 0; n4 < 8; n4++) {
                int nb = wn * 64 + n4 * 8 + lg;
                bb[n4][0] = fau(Bb[kq * 136 + nb]);
                bb[n4][1] = fau(Bb[(kq + 4) * 136 + nb]);
            }
#pragma unroll
            for (int mt = 0; mt < 2; mt++)
#pragma unroll
                for (int n4 = 0; n4 < 8; n4++)
                    MMA_TF32(c[mt][n4], a[mt], bb[n4]);
        }
        __syncthreads();
    }
    int SB = c_TB[ib];
    bool isz = (nt >= 2);
#pragma unroll
    for (int mt = 0; mt < 2; mt++)
#pragma unroll
        for (int n4 = 0; n4 < 8; n4++) {
            int row = t0 + wm * 32 + mt * 16 + lg;
            int col = nt * 128 + wn * 64 + n4 * 8 + 2 * lt;
            float2 v0 = make_float2(c[mt][n4][0], c[mt][n4][1]);
            float2 v1 = make_float2(c[mt][n4][2], c[mt][n4][3]);
            if (isz) {
                v0.x = siluf(v0.x); v0.y = siluf(v0.y);
                v1.x = siluf(v1.x); v1.y = siluf(v1.y);
            }
            *(float2*)&g_XZ[(SB + row) * 512 + col]     = v0;
            *(float2*)&g_XZ[(SB + row + 8) * 512 + col] = v1;
        }
}

// ---------------------------------------------------------------------------
// K2: causal conv(4)+silu -> XS (tf32-rounded) token-major.
// ---------------------------------------------------------------------------
__global__ void k_conv(const float* __restrict__ cw, const float* __restrict__ cb) {
    int tc = blockIdx.x, ib = blockIdx.y;
    int i = ib >> 2;
    int T = scanT(i);
    if (tc * 64 >= T) return;
    int d = threadIdx.x;
    int SB = c_TB[ib];
    const float* w = &cw[(i * 256 + d) * 4];
    float w0 = w[0], w1 = w[1], w2 = w[2], w3 = w[3];
    float bias = cb[i * 256 + d];
    const float* px = &g_XZ[SB * 512 + d];
    float* pxs = &g_XS[SB * 256 + d];
    int t0 = tc * 64;
    float xm1 = (t0 >= 1) ? px[(t0 - 1) * 512] : 0.0f;
    float xm2 = (t0 >= 2) ? px[(t0 - 2) * 512] : 0.0f;
    float xm3 = (t0 >= 3) ? px[(t0 - 3) * 512] : 0.0f;
    for (int q4 = 0; q4 < 16; q4++) {
        float xv[4];
#pragma unroll
        for (int j = 0; j < 4; j++) xv[j] = px[(t0 + q4 * 4 + j) * 512];
#pragma unroll
        for (int j = 0; j < 4; j++) {
            float x = xv[j];
            float acc = fmaf(x, w3, fmaf(xm1, w2, fmaf(xm2, w1, fmaf(xm3, w0, bias))));
            pxs[(t0 + q4 * 4 + j) * 256] = tf(siluf(acc));
            xm3 = xm2; xm2 = xm1; xm1 = x;
        }
    }
}

// ---------------------------------------------------------------------------
// K3: x_proj tf32 GEMM.  128x64 tile, K=256, 2-stage cp.async pipeline.
// ---------------------------------------------------------------------------
#define XP_ASZ (128 * 36)
#define XP_BSZ (32 * 72)
__global__ void __launch_bounds__(256, 2) k_gemm_xp() {
    extern __shared__ float dsm[];
    float* Asm = dsm;
    float* Bsm = dsm + 2 * XP_ASZ;
    int tt = blockIdx.y;
    int ib = blockIdx.z;
    int i = ib >> 2;
    int T = scanT(i);
    if (tt * 128 >= T) return;
    int t0 = tt * 128;
    int SB = c_TB[ib];
    int tid = threadIdx.x;
    int warp = tid >> 5, lane = tid & 31;
    int wm = warp & 3, wn = warp >> 2;
    int lg = lane >> 2, lt = lane & 3;

    auto load_stage = [&](int st, int kc) {
#pragma unroll
        for (int p = 0; p < 4; p++) {
            int q = p * 256 + tid;
            int kk4 = q & 7, m = q >> 3;
            cpa16(&Asm[st * XP_ASZ + m * 36 + kk4 * 4],
                  &g_XS[(SB + t0 + m) * 256 + kc * 32 + kk4 * 4]);
        }
#pragma unroll
        for (int p = 0; p < 2; p++) {
            int q = p * 256 + tid;
            int n4 = q & 15, kk = q >> 4;
            cpa16(&Bsm[st * XP_BSZ + kk * 72 + n4 * 4],
                  &g_WTxp[(i * 256 + kc * 32 + kk) * 64 + n4 * 4]);
        }
    };

    float c[2][4][4] = {};
    load_stage(0, 0); CP_COMMIT();
    for (int kc = 0; kc < 8; kc++) {
        if (kc + 1 < 8) { load_stage((kc + 1) & 1, kc + 1); CP_COMMIT(); CP_WAIT1(); }
        else CP_WAIT0();
        __syncthreads();
        const float* Ab = &Asm[(kc & 1) * XP_ASZ];
        const float* Bb = &Bsm[(kc & 1) * XP_BSZ];
#pragma unroll
        for (int k8 = 0; k8 < 4; k8++) {
            int kq = k8 * 8 + lt;
            uint32_t a[2][4];
#pragma unroll
            for (int mt = 0; mt < 2; mt++) {
                int mr = wm * 32 + mt * 16 + lg;
                a[mt][0] = fau(Ab[mr * 36 + kq]);       a[mt][1] = fau(Ab[(mr + 8) * 36 + kq]);
                a[mt][2] = fau(Ab[mr * 36 + kq + 4]);   a[mt][3] = fau(Ab[(mr + 8) * 36 + kq + 4]);
            }
            uint32_t bb[4][2];
#pragma unroll
            for (int n4 = 0; n4 < 4; n4++) {
                int nb = wn * 32 + n4 * 8 + lg;
                bb[n4][0] = fau(Bb[kq * 72 + nb]);
                bb[n4][1] = fau(Bb[(kq + 4) * 72 + nb]);
            }
#pragma unroll
            for (int mt = 0; mt < 2; mt++)
#pragma unroll
                for (int n4 = 0; n4 < 4; n4++)
                    MMA_TF32(c[mt][n4], a[mt], bb[n4]);
        }
        __syncthreads();
    }
#pragma unroll
    for (int mt = 0; mt < 2; mt++)
#pragma unroll
        for (int n4 = 0; n4 < 4; n4++) {
            int row = t0 + wm * 32 + mt * 16 + lg;
            int col = wn * 32 + n4 * 8 + 2 * lt;
            if (col < 40) {
                *(float2*)&g_XDBL[(SB + row) * 40 + col]     = make_float2(c[mt][n4][0], c[mt][n4][1]);
                *(float2*)&g_XDBL[(SB + row + 8) * 40 + col] = make_float2(c[mt][n4][2], c[mt][n4][3]);
            }
        }
}

// ---------------------------------------------------------------------------
// K5a: chunk-local scan (delta fused inline). thread=d.
// ---------------------------------------------------------------------------
__global__ void k_scan1(const float* __restrict__ alog,
                        const float* __restrict__ dtw, const float* __restrict__ dtb) {
    int c = blockIdx.x, ib = blockIdx.y;
    int i = ib >> 2;
    int T = scanT(i);
    int LC = T / NCHUNK;
    int d = threadIdx.x;
    int SB = c_TB[ib];
    bool pw = (g_powBad == 0);
    float A0 = -__expf(alog[(i * 256 + d) * 16]);
    float4 dw0 = *(const float4*)&dtw[(i * 256 + d) * 8];
    float4 dw1 = *(const float4*)&dtw[(i * 256 + d) * 8 + 4];
    float dbias = dtb[i * 256 + d];
    const float* pU = &g_XS[SB * 256 + d];
    const float* pBC = &g_XDBL[SB * 40];
    float h[16];
#pragma unroll
    for (int s = 0; s < 16; s++) h[s] = 0.0f;
    float dsum = 0.0f;
    int t0 = c * LC;
    if (pw) {
#pragma unroll 2
        for (int t = t0; t < t0 + LC; t++) {
            const float4* r = (const float4*)&pBC[t * 40];
            float4 a0 = r[0], a1 = r[1];
            float pre = dbias;
            pre = fmaf(a0.x, dw0.x, pre); pre = fmaf(a0.y, dw0.y, pre);
            pre = fmaf(a0.z, dw0.z, pre); pre = fmaf(a0.w, dw0.w, pre);
            pre = fmaf(a1.x, dw1.x, pre); pre = fmaf(a1.y, dw1.y, pre);
            pre = fmaf(a1.z, dw1.z, pre); pre = fmaf(a1.w, dw1.w, pre);
            float dv = softplusf(pre);
            float du = dv * pU[t * 256];
            dsum += dv;
            float q = __expf(dv * A0);
            float4 B0 = r[2], B1 = r[3], B2 = r[4], B3 = r[5];
            float ap = q;
            h[0]  = fmaf(ap, h[0],  du * B0.x); ap *= q;
            h[1]  = fmaf(ap, h[1],  du * B0.y); ap *= q;
            h[2]  = fmaf(ap, h[2],  du * B0.z); ap *= q;
            h[3]  = fmaf(ap, h[3],  du * B0.w); ap *= q;
            h[4]  = fmaf(ap, h[4],  du * B1.x); ap *= q;
            h[5]  = fmaf(ap, h[5],  du * B1.y); ap *= q;
            h[6]  = fmaf(ap, h[6],  du * B1.z); ap *= q;
            h[7]  = fmaf(ap, h[7],  du * B1.w); ap *= q;
            h[8]  = fmaf(ap, h[8],  du * B2.x); ap *= q;
            h[9]  = fmaf(ap, h[9],  du * B2.y); ap *= q;
            h[10] = fmaf(ap, h[10], du * B2.z); ap *= q;
            h[11] = fmaf(ap, h[11], du * B2.w); ap *= q;
            h[12] = fmaf(ap, h[12], du * B3.x); ap *= q;
            h[13] = fmaf(ap, h[13], du * B3.y); ap *= q;
            h[14] = fmaf(ap, h[14], du * B3.z); ap *= q;
            h[15] = fmaf(ap, h[15], du * B3.w);
        }
    } else {
        float As[16];
#pragma unroll
        for (int s = 0; s < 16; s++) As[s] = -__expf(alog[(i * 256 + d) * 16 + s]);
        for (int t = t0; t < t0 + LC; t++) {
            const float4* r = (const float4*)&pBC[t * 40];
            float4 a0 = r[0], a1 = r[1];
            float pre = dbias;
            pre = fmaf(a0.x, dw0.x, pre); pre = fmaf(a0.y, dw0.y, pre);
            pre = fmaf(a0.z, dw0.z, pre); pre = fmaf(a0.w, dw0.w, pre);
            pre = fmaf(a1.x, dw1.x, pre); pre = fmaf(a1.y, dw1.y, pre);
            pre = fmaf(a1.z, dw1.z, pre); pre = fmaf(a1.w, dw1.w, pre);
            float dv = softplusf(pre);
            float du = dv * pU[t * 256];
            dsum += dv;
            const float* Bp = &pBC[t * 40 + 8];
#pragma unroll
            for (int s = 0; s < 16; s++) {
                float a = __expf(dv * As[s]);
                h[s] = fmaf(a, h[s], du * Bp[s]);
            }
        }
    }
    int base = ((ib * NCHUNK + c) * 256 + d) * 16;
#pragma unroll
    for (int s = 0; s < 16; s++) {
        float Ascale = pw ? (A0 * (float)(s + 1))
                          : (-__expf(alog[(i * 256 + d) * 16 + s]));
        g_CP[base + s] = __expf(Ascale * dsum);
        g_CH[base + s] = h[s];
    }
}

// ---------------------------------------------------------------------------
// K5b: prefix over chunks
// ---------------------------------------------------------------------------
__global__ void k_scan2() {
    int g = blockIdx.x * 256 + threadIdx.x;
    int ib = g >> 12;
    int rem = g & 4095;
    float hi = 0.0f;
    for (int c = 0; c < NCHUNK; c++) {
        int idx = ib * (NCHUNK * 4096) + c * 4096 + rem;
        g_HI[idx] = hi;
        hi = fmaf(g_CP[idx], hi, g_CH[idx]);
    }
}

// ---------------------------------------------------------------------------
// K5c: chunk recompute with true h_init; y -> YT (tf32-rounded) token-major.
// ---------------------------------------------------------------------------
__global__ void k_scan3(const float* __restrict__ alog, const float* __restrict__ Dv,
                        const float* __restrict__ dtw, const float* __restrict__ dtb) {
    int c = blockIdx.x, ib = blockIdx.y;
    int i = ib >> 2;
    int T = scanT(i);
    int LC = T / NCHUNK;
    int d = threadIdx.x;
    int SB = c_TB[ib];
    bool pw = (g_powBad == 0);
    float A0 = -__expf(alog[(i * 256 + d) * 16]);
    float Dreg = Dv[i * 256 + d];
    float4 dw0 = *(const float4*)&dtw[(i * 256 + d) * 8];
    float4 dw1 = *(const float4*)&dtw[(i * 256 + d) * 8 + 4];
    float dbias = dtb[i * 256 + d];
    const float* pU = &g_XS[SB * 256 + d];
    const float* pZ = &g_XZ[SB * 512 + 256 + d];
    const float* pBC = &g_XDBL[SB * 40];
    float* pY = &g_YT[SB * 256 + d];
    float h[16];
    {
        int base = ((ib * NCHUNK + c) * 256 + d) * 16;
#pragma unroll
        for (int s = 0; s < 16; s++) h[s] = g_HI[base + s];
    }
    int t0 = c * LC;
    if (pw) {
#pragma unroll 2
        for (int t = t0; t < t0 + LC; t++) {
            const float4* r = (const float4*)&pBC[t * 40];
            float4 a0 = r[0], a1 = r[1];
            float pre = dbias;
            pre = fmaf(a0.x, dw0.x, pre); pre = fmaf(a0.y, dw0.y, pre);
            pre = fmaf(a0.z, dw0.z, pre); pre = fmaf(a0.w, dw0.w, pre);
            pre = fmaf(a1.x, dw1.x, pre); pre = fmaf(a1.y, dw1.y, pre);
            pre = fmaf(a1.z, dw1.z, pre); pre = fmaf(a1.w, dw1.w, pre);
            float dv = softplusf(pre);
            float u = pU[t * 256];
            float du = dv * u;
            float q = __expf(dv * A0);
            float4 B0 = r[2], B1 = r[3], B2 = r[4], B3 = r[5];
            float4 C0 = r[6], C1 = r[7], C2 = r[8], C3 = r[9];
            float ys = 0.0f;
            float ap = q;
            h[0]  = fmaf(ap, h[0],  du * B0.x); ys = fmaf(h[0],  C0.x, ys); ap *= q;
            h[1]  = fmaf(ap, h[1],  du * B0.y); ys = fmaf(h[1],  C0.y, ys); ap *= q;
            h[2]  = fmaf(ap, h[2],  du * B0.z); ys = fmaf(h[2],  C0.z, ys); ap *= q;
            h[3]  = fmaf(ap, h[3],  du * B0.w); ys = fmaf(h[3],  C0.w, ys); ap *= q;
            h[4]  = fmaf(ap, h[4],  du * B1.x); ys = fmaf(h[4],  C1.x, ys); ap *= q;
            h[5]  = fmaf(ap, h[5],  du * B1.y); ys = fmaf(h[5],  C1.y, ys); ap *= q;
            h[6]  = fmaf(ap, h[6],  du * B1.z); ys = fmaf(h[6],  C1.z, ys); ap *= q;
            h[7]  = fmaf(ap, h[7],  du * B1.w); ys = fmaf(h[7],  C1.w, ys); ap *= q;
            h[8]  = fmaf(ap, h[8],  du * B2.x); ys = fmaf(h[8],  C2.x, ys); ap *= q;
            h[9]  = fmaf(ap, h[9],  du * B2.y); ys = fmaf(h[9],  C2.y, ys); ap *= q;
            h[10] = fmaf(ap, h[10], du * B2.z); ys = fmaf(h[10], C2.z, ys); ap *= q;
            h[11] = fmaf(ap, h[11], du * B2.w); ys = fmaf(h[11], C2.w, ys); ap *= q;
            h[12] = fmaf(ap, h[12], du * B3.x); ys = fmaf(h[12], C3.x, ys); ap *= q;
            h[13] = fmaf(ap, h[13], du * B3.y); ys = fmaf(h[13], C3.y, ys); ap *= q;
            h[14] = fmaf(ap, h[14], du * B3.z); ys = fmaf(h[14], C3.z, ys); ap *= q;
            h[15] = fmaf(ap, h[15], du * B3.w); ys = fmaf(h[15], C3.w, ys);
            float z = pZ[t * 512];
            pY[t * 256] = tf(fmaf(u, Dreg, ys) * z);
        }
    } else {
        float As[16];
#pragma unroll
        for (int s = 0; s < 16; s++) As[s] = -__expf(alog[(i * 256 + d) * 16 + s]);
        for (int t = t0; t < t0 + LC; t++) {
            const float4* r = (const float4*)&pBC[t * 40];
            float4 a0 = r[0], a1 = r[1];
            float pre = dbias;
            pre = fmaf(a0.x, dw0.x, pre); pre = fmaf(a0.y, dw0.y, pre);
            pre = fmaf(a0.z, dw0.z, pre); pre = fmaf(a0.w, dw0.w, pre);
            pre = fmaf(a1.x, dw1.x, pre); pre = fmaf(a1.y, dw1.y, pre);
            pre = fmaf(a1.z, dw1.z, pre); pre = fmaf(a1.w, dw1.w, pre);
            float dv = softplusf(pre);
            float u = pU[t * 256];
            float du = dv * u;
            const float* Bp = &pBC[t * 40 + 8];
            float ys = 0.0f;
#pragma unroll
            for (int s = 0; s < 16; s++) {
                float a = __expf(dv * As[s]);
                h[s] = fmaf(a, h[s], du * Bp[s]);
                ys = fmaf(h[s], Bp[16 + s], ys);
            }
            float z = pZ[t * 512];
            pY[t * 256] = tf(fmaf(u, Dreg, ys) * z);
        }
    }
}

// ---------------------------------------------------------------------------
// K6: out_proj tf32 GEMM.  128x128 tile, K=256, 2-stage cp.async pipeline.
// ---------------------------------------------------------------------------
__global__ void __launch_bounds__(256, 2) k_gemm_out() {
    extern __shared__ float dsm[];
    float* Asm = dsm;
    float* Bsm = dsm + 2 * IN_ASZ;
    int tt = blockIdx.y;
    int ib = blockIdx.z;
    int i = ib >> 2;
    int T = scanT(i);
    if (tt * 128 >= T) return;
    int t0 = tt * 128;
    int SB = c_TB[ib];
    int tid = threadIdx.x;
    int warp = tid >> 5, lane = tid & 31;
    int wm = warp & 3, wn = warp >> 2;
    int lg = lane >> 2, lt = lane & 3;

    auto load_stage = [&](int st, int kc) {
#pragma unroll
        for (int p = 0; p < 4; p++) {
            int q = p * 256 + tid;
            int kk4 = q & 7, m = q >> 3;
            cpa16(&Asm[st * IN_ASZ + m * 36 + kk4 * 4],
                  &g_YT[(SB + t0 + m) * 256 + kc * 32 + kk4 * 4]);
        }
#pragma unroll
        for (int p = 0; p < 4; p++) {
            int q = p * 256 + tid;
            int n4 = q & 31, kk = q >> 5;
            cpa16(&Bsm[st * IN_BSZ + kk * 136 + n4 * 4],
                  &g_WTout[(i * 256 + kc * 32 + kk) * 128 + n4 * 4]);
        }
    };

    float c[2][8][4] = {};
    load_stage(0, 0); CP_COMMIT();
    for (int kc = 0; kc < 8; kc++) {
        if (kc + 1 < 8) { load_stage((kc + 1) & 1, kc + 1); CP_COMMIT(); CP_WAIT1(); }
        else CP_WAIT0();
        __syncthreads();
        const float* Ab = &Asm[(kc & 1) * IN_ASZ];
        const float* Bb = &Bsm[(kc & 1) * IN_BSZ];
#pragma unroll
        for (int k8 = 0; k8 < 4; k8++) {
            int kq = k8 * 8 + lt;
            uint32_t a[2][4];
#pragma unroll
            for (int mt = 0; mt < 2; mt++) {
                int mr = wm * 32 + mt * 16 + lg;
                a[mt][0] = fau(Ab[mr * 36 + kq]);       a[mt][1] = fau(Ab[(mr + 8) * 36 + kq]);
                a[mt][2] = fau(Ab[mr * 36 + kq + 4]);   a[mt][3] = fau(Ab[(mr + 8) * 36 + kq + 4]);
            }
            uint32_t bb[8][2];
#pragma unroll
            for (int n4 = 0; n4 < 8; n4++) {
                int nb = wn * 64 + n4 * 8 + lg;
                bb[n4][0] = fau(Bb[kq * 136 + nb]);
                bb[n4][1] = fau(Bb[(kq + 4) * 136 + nb]);
            }
#pragma unroll
            for (int mt = 0; mt < 2; mt++)
#pragma unroll
                for (int n4 = 0; n4 < 8; n4++)
                    MMA_TF32(c[mt][n4], a[mt], bb[n4]);
        }
        __syncthreads();
    }
#pragma unroll
    for (int mt = 0; mt < 2; mt++)
#pragma unroll
        for (int n4 = 0; n4 < 8; n4++) {
            int row = t0 + wm * 32 + mt * 16 + lg;
            int col = wn * 64 + n4 * 8 + 2 * lt;
            *(float2*)&g_OUT[(SB + row) * 128 + col]     = make_float2(c[mt][n4][0], c[mt][n4][1]);
            *(float2*)&g_OUT[(SB + row + 8) * 128 + col] = make_float2(c[mt][n4][2], c[mt][n4][3]);
        }
}

// interp of backward-scan output
__device__ __forceinline__ float interp_flip(int i, int b, int l, int c) {
    float pos = 0.5f * (float)(8191 - l) - 0.25f;
    pos = fminf(fmaxf(pos, 0.0f), 4095.0f);
    int lo = (int)floorf(pos);
    int hi = min(lo + 1, 4095);
    float w = pos - (float)lo;
    const float* ob = &g_OUT[c_TB[i * 4 + b] * 128 + c];
    return ob[lo * 128] * (1.0f - w) + ob[hi * 128] * w;
}

// ---------------------------------------------------------------------------
// K7: merge 4 scan outputs -> a,b maps [2][B][C][64][64]
// ---------------------------------------------------------------------------
__global__ void k_merge() {
    __shared__ float S[64][129];
    int irow = blockIdx.x;
    int b = blockIdx.y;
    int tid = threadIdx.x;
    for (int half = 0; half < 2; half++) {
        for (int p = 0; p < 32; p++) {
            int idx = p * 256 + tid;
            int c = idx & 127, j = idx >> 7;
            int l  = irow * 128 + j + (half ? 64 : 0);
            int l2 = j * 128 + irow + (half ? 64 : 0);
            float v = g_OUT[(c_TB[b] + l) * 128 + c];
            v += interp_flip(1, b, l, c);
            v += g_OUT[(c_TB[8 + b] + l2) * 128 + c];
            v += interp_flip(3, b, l2, c);
            S[j][c] = v;
        }
        __syncthreads();
        for (int p = 0; p < 32; p++) {
            int idx = p * 256 + tid;
            int j = idx & 63, c = idx >> 6;
            g_AB[((half * 4 + b) * 128 + c) * 4096 + irow * 64 + j] = S[j][c];
        }
        __syncthreads();
    }
}

// ---------------------------------------------------------------------------
// K8: bilinear 64->128 upsample + residuals
// ---------------------------------------------------------------------------
__global__ void k_final(const float* __restrict__ fa, const float* __restrict__ fb,
                        float* __restrict__ out) {
    int idx = blockIdx.x * 256 + threadIdx.x;
    int w = idx & 127, hh = (idx >> 7) & 127, c = (idx >> 14) & 127, b = idx >> 21;
    float ph = fminf(fmaxf(0.5f * hh - 0.25f, 0.0f), 63.0f);
    int h0 = (int)floorf(ph); int h1 = min(h0 + 1, 63); float wh = ph - (float)h0;
    float pw = fminf(fmaxf(0.5f * w - 0.25f, 0.0f), 63.0f);
    int w0 = (int)floorf(pw); int w1 = min(w0 + 1, 63); float ww = pw - (float)w0;
    const float* Aa = &g_AB[((0 * 4 + b) * 128 + c) * 4096];
    const float* Bb = &g_AB[((1 * 4 + b) * 128 + c) * 4096];
    float av = (Aa[h0 * 64 + w0] * (1.0f - ww) + Aa[h0 * 64 + w1] * ww) * (1.0f - wh)
             + (Aa[h1 * 64 + w0] * (1.0f - ww) + Aa[h1 * 64 + w1] * ww) * wh;
    float bv = (Bb[h0 * 64 + w0] * (1.0f - ww) + Bb[h0 * 64 + w1] * ww) * (1.0f - wh)
             + (Bb[h1 * 64 + w0] * (1.0f - ww) + Bb[h1 * 64 + w1] * ww) * wh;
    out[idx] = av + bv + fa[idx] + fb[idx];
}

// ---------------------------------------------------------------------------
extern "C" void kernel_launch(void* const* d_in, const int* in_sizes, int n_in,
                              void* d_out, int out_size) {
    (void)in_sizes; (void)n_in; (void)out_size;
    const float* fa   = (const float*)d_in[0];
    const float* fb   = (const float*)d_in[1];
    const float* inw  = (const float*)d_in[2];
    const float* cw   = (const float*)d_in[3];
    const float* cb   = (const float*)d_in[4];
    const float* xpw  = (const float*)d_in[5];
    const float* dtw  = (const float*)d_in[6];
    const float* dtb  = (const float*)d_in[7];
    const float* alog = (const float*)d_in[8];
    const float* Dv   = (const float*)d_in[9];
    const float* outw = (const float*)d_in[10];
    float* out = (float*)d_out;

    const int SMEM_IN  = 2 * (IN_ASZ + IN_BSZ) * 4;   // 71680
    const int SMEM_XP  = 2 * (XP_ASZ + XP_BSZ) * 4;   // 55296
    cudaFuncSetAttribute(k_gemm_in,  cudaFuncAttributeMaxDynamicSharedMemorySize, SMEM_IN);
    cudaFuncSetAttribute(k_gemm_xp,  cudaFuncAttributeMaxDynamicSharedMemorySize, SMEM_XP);
    cudaFuncSetAttribute(k_gemm_out, cudaFuncAttributeMaxDynamicSharedMemorySize, SMEM_IN);

    k_gather<<<dim3(2, 64, 4), 256>>>(fa, fb);
    k_prep_w<<<1024, 256>>>(inw, xpw, outw);
    k_prep_chk<<<64, 256>>>(alog);
    k_gemm_in<<<dim3(4, 64, 16), 256, SMEM_IN>>>();
    k_conv<<<dim3(128, 16), 256>>>(cw, cb);
    k_gemm_xp<<<dim3(1, 64, 16), 256, SMEM_XP>>>();
    k_scan1<<<dim3(NCHUNK, 16), 256>>>(alog, dtw, dtb);
    k_scan2<<<256, 256>>>();
    k_scan3<<<dim3(NCHUNK, 16), 256>>>(alog, Dv, dtw, dtb);
    k_gemm_out<<<dim3(1, 64, 16), 256, SMEM_IN>>>();
    k_merge<<<dim3(64, 4), 256>>>();
    k_final<<<32768, 256>>>(fa, fb, out);
}

// round 11
// speedup vs baseline: 1.2694x; 1.1824x over previous
#include <cuda_runtime.h>
#include <cuda_fp16.h>
#include <math.h>
#include <stdint.h>

// ---------------------------------------------------------------------------
// JointMambaFusion: B=4, C=128, H=W=128, D_INNER=256, D_STATE=16, DT_RANK=8
// 4 scans: T = {8192, 4096, 8192, 4096}; token bases c_TB[ib], TOKTOT tokens.
// fp16 tensor-core GEMMs (m16n8k16, fp32 accum) with 2-stage cp.async
// pipelines. Scan math fp32; fp16 storage for X/XZ/XS/YT.
// ---------------------------------------------------------------------------

#define TOKTOT 98304
#define NCHUNK 32

__constant__ int c_TB[16] = {
    0,     8192,  16384, 24576,
    32768, 36864, 40960, 45056,
    49152, 57344, 65536, 73728,
    81920, 86016, 90112, 94208
};

__device__ __half g_X    [4 * 8192 * 128];   // gathered h-scan layout
__device__ __half g_XZ   [TOKTOT * 512];     // xl | silu(z)
__device__ __half g_XS   [TOKTOT * 256];     // u
__device__ float  g_XDBL [TOKTOT * 40];      // dt | B | C (fp32)
__device__ __half g_YT   [TOKTOT * 256];     // y
__device__ float  g_OUT  [TOKTOT * 128];
__device__ float  g_AB   [2 * 4 * 128 * 64 * 64];
__device__ __half g_WTinH [4 * 512 * 128];   // [i][n=512][k=128]
__device__ __half g_WTxpH [4 * 64 * 256];    // [i][n=64][k=256] (rows>=40 zero)
__device__ __half g_WToutH[4 * 128 * 256];   // [i][n=128][k=256]
__device__ float g_CP [16 * NCHUNK * 256 * 16];
__device__ float g_CH [16 * NCHUNK * 256 * 16];
__device__ float g_HI [16 * NCHUNK * 256 * 16];
__device__ int   g_powBad = 0;

__device__ __forceinline__ int scanT(int i) { return (i & 1) ? 4096 : 8192; }

__device__ __forceinline__ float siluf(float x) {
    return __fdividef(x, 1.0f + __expf(-x));
}
__device__ __forceinline__ float softplusf(float x) {
    return (x > 15.0f) ? x : __logf(1.0f + __expf(x));
}

__device__ __forceinline__ void cpa16(void* dst_smem, const void* src) {
    uint32_t dst = (uint32_t)__cvta_generic_to_shared(dst_smem);
    asm volatile("cp.async.cg.shared.global [%0], [%1], 16;" :: "r"(dst), "l"(src));
}
#define CP_COMMIT() asm volatile("cp.async.commit_group;" ::: "memory")
#define CP_WAIT1()  asm volatile("cp.async.wait_group 1;" ::: "memory")
#define CP_WAIT0()  asm volatile("cp.async.wait_group 0;" ::: "memory")

#define MMA_F16(C, A, B)                                                      \
    asm volatile("mma.sync.aligned.m16n8k16.row.col.f32.f16.f16.f32 "         \
        "{%0,%1,%2,%3},{%4,%5,%6,%7},{%8,%9},{%0,%1,%2,%3};"                  \
        : "+f"((C)[0]), "+f"((C)[1]), "+f"((C)[2]), "+f"((C)[3])              \
        : "r"((A)[0]), "r"((A)[1]), "r"((A)[2]), "r"((A)[3]),                 \
          "r"((B)[0]), "r"((B)[1]))

__device__ __forceinline__ uint32_t ldh2(const __half* p) {
    return *(const uint32_t*)p;
}

// row in X_h for (scan i, token t)
__device__ __forceinline__ int rowmap(int i, int t) {
    if (i == 0) return t;
    if (i == 1) return 8191 - 2 * t;
    int l = (i == 2) ? t : (8191 - 2 * t);
    int ww = l >> 7, rr = l & 127;
    return (rr < 64) ? rr * 128 + ww : (rr - 64) * 128 + ww + 64;
}

// ---------------------------------------------------------------------------
// K-1: gather h-scan layout X_h[b][t=hh*128+ww][c] (fp16)
// ---------------------------------------------------------------------------
__global__ void k_gather(const float* __restrict__ fa, const float* __restrict__ fb) {
    __shared__ float S[64][129];
    int half_ = blockIdx.x;
    int hh = blockIdx.y;
    int b = blockIdx.z;
    int tid = threadIdx.x;
    int warp = tid >> 5, lane = tid & 31;
    for (int j = 0; j < 16; j++) {
        int c = warp * 16 + j;
        int planebase = (b * 128 + c) * 16384 + 2 * hh * 128;
        for (int it = 0; it < 2; it++) {
            int wl = it * 32 + lane;
            int ww = half_ * 64 + wl;
            float v = (ww < 64) ? fa[planebase + 2 * ww]
                                : fb[planebase + 2 * ww - 128];
            S[wl][c] = v;
        }
    }
    __syncthreads();
    int base = (b * 8192 + hh * 128 + half_ * 64) * 128;
    for (int q = 0; q < 16; q++) {        // 4096 half2 pairs
        int idx = q * 256 + tid;
        int c2 = idx & 63, row = idx >> 6;
        half2 v = __floats2half2_rn(S[row][c2 * 2], S[row][c2 * 2 + 1]);
        *(half2*)&g_X[base + row * 128 + c2 * 2] = v;
    }
}

// ---------------------------------------------------------------------------
// K0a: weight fp16 conversion (layouts are already [n][k])
// ---------------------------------------------------------------------------
__global__ void k_prep_w(const float* __restrict__ inw,
                         const float* __restrict__ xpw,
                         const float* __restrict__ outw) {
    int idx = blockIdx.x * 256 + threadIdx.x;
    if (idx < 4 * 512 * 128)
        g_WTinH[idx] = __float2half_rn(inw[idx]);
    if (idx < 4 * 64 * 256) {
        int i = idx / (64 * 256), r = idx % (64 * 256);
        int e = r / 256, cd = r % 256;
        g_WTxpH[idx] = (e < 40) ? __float2half_rn(xpw[(i * 40 + e) * 256 + cd])
                                : __float2half_rn(0.0f);
    }
    if (idx < 4 * 128 * 256)
        g_WToutH[idx] = __float2half_rn(outw[idx]);
}

// K0b: A_log structure check
__global__ void k_prep_chk(const float* __restrict__ alog) {
    int idx = blockIdx.x * 256 + threadIdx.x;
    if (idx < 4 * 256 * 16) {
        int s = idx & 15;
        int dI = idx >> 4;
        float As = -__expf(alog[dI * 16 + s]);
        float A0 = -__expf(alog[dI * 16]);
        float ratio = As / A0;
        if (fabsf(ratio - (float)(s + 1)) > 1e-5f * (float)(s + 1))
            atomicOr(&g_powBad, 1);
    }
}

// ---------------------------------------------------------------------------
// K1: in_proj fp16 GEMM.  128x128 tile, K=128 (2 stages of 64).
// z half (nt>=2) silu'd in epilogue.
// ---------------------------------------------------------------------------
#define IN_A_H (128 * 72)
#define IN_B_H (128 * 72)
__global__ void __launch_bounds__(256, 2) k_gemm_in() {
    extern __shared__ __half hsm[];
    __half* Asm = hsm;                  // [2][128][72]
    __half* Bsm = hsm + 2 * IN_A_H;     // [2][128][72]
    int nt = blockIdx.x;                // 0..3
    int tt = blockIdx.y;
    int ib = blockIdx.z;
    int i = ib >> 2, b = ib & 3;
    int T = scanT(i);
    if (tt * 128 >= T) return;
    int t0 = tt * 128;
    int tid = threadIdx.x;
    int warp = tid >> 5, lane = tid & 31;
    int wm = warp & 3, wn = warp >> 2;
    int lg = lane >> 2, lt = lane & 3;

    auto load_stage = [&](int st, int kc) {
#pragma unroll
        for (int p = 0; p < 4; p++) {
            int q = p * 256 + tid;
            int ch = q & 7, m = q >> 3;
            int r = rowmap(i, t0 + m);
            cpa16(&Asm[st * IN_A_H + m * 72 + ch * 8],
                  &g_X[(b * 8192 + r) * 128 + kc * 64 + ch * 8]);
        }
#pragma unroll
        for (int p = 0; p < 4; p++) {
            int q = p * 256 + tid;
            int ch = q & 7, n = q >> 3;
            cpa16(&Bsm[st * IN_B_H + n * 72 + ch * 8],
                  &g_WTinH[(i * 512 + nt * 128 + n) * 128 + kc * 64 + ch * 8]);
        }
    };

    float c[2][8][4] = {};
    load_stage(0, 0); CP_COMMIT();
    for (int kc = 0; kc < 2; kc++) {
        if (kc + 1 < 2) { load_stage((kc + 1) & 1, kc + 1); CP_COMMIT(); CP_WAIT1(); }
        else CP_WAIT0();
        __syncthreads();
        const __half* Ab = &Asm[(kc & 1) * IN_A_H];
        const __half* Bb = &Bsm[(kc & 1) * IN_B_H];
#pragma unroll
        for (int j = 0; j < 4; j++) {               // k16 steps
            int kb = j * 16 + 2 * lt;
            uint32_t a[2][4];
#pragma unroll
            for (int mt = 0; mt < 2; mt++) {
                int mr = wm * 32 + mt * 16 + lg;
                a[mt][0] = ldh2(&Ab[mr * 72 + kb]);
                a[mt][1] = ldh2(&Ab[(mr + 8) * 72 + kb]);
                a[mt][2] = ldh2(&Ab[mr * 72 + kb + 8]);
                a[mt][3] = ldh2(&Ab[(mr + 8) * 72 + kb + 8]);
            }
            uint32_t bb[8][2];
#pragma unroll
            for (int n4 = 0; n4 < 8; n4++) {
                int nb = wn * 64 + n4 * 8 + lg;
                bb[n4][0] = ldh2(&Bb[nb * 72 + kb]);
                bb[n4][1] = ldh2(&Bb[nb * 72 + kb + 8]);
            }
#pragma unroll
            for (int mt = 0; mt < 2; mt++)
#pragma unroll
                for (int n4 = 0; n4 < 8; n4++)
                    MMA_F16(c[mt][n4], a[mt], bb[n4]);
        }
        __syncthreads();
    }
    int SB = c_TB[ib];
    bool isz = (nt >= 2);
#pragma unroll
    for (int mt = 0; mt < 2; mt++)
#pragma unroll
        for (int n4 = 0; n4 < 8; n4++) {
            int row = t0 + wm * 32 + mt * 16 + lg;
            int col = nt * 128 + wn * 64 + n4 * 8 + 2 * lt;
            float v0 = c[mt][n4][0], v1 = c[mt][n4][1];
            float v2 = c[mt][n4][2], v3 = c[mt][n4][3];
            if (isz) { v0 = siluf(v0); v1 = siluf(v1); v2 = siluf(v2); v3 = siluf(v3); }
            *(half2*)&g_XZ[(SB + row) * 512 + col]     = __floats2half2_rn(v0, v1);
            *(half2*)&g_XZ[(SB + row + 8) * 512 + col] = __floats2half2_rn(v2, v3);
        }
}

// ---------------------------------------------------------------------------
// K2: causal conv(4)+silu -> XS (fp16) token-major.
// ---------------------------------------------------------------------------
__global__ void k_conv(const float* __restrict__ cw, const float* __restrict__ cb) {
    int tc = blockIdx.x, ib = blockIdx.y;
    int i = ib >> 2;
    int T = scanT(i);
    if (tc * 64 >= T) return;
    int d = threadIdx.x;
    int SB = c_TB[ib];
    const float* w = &cw[(i * 256 + d) * 4];
    float w0 = w[0], w1 = w[1], w2 = w[2], w3 = w[3];
    float bias = cb[i * 256 + d];
    const __half* px = &g_XZ[SB * 512 + d];
    __half* pxs = &g_XS[SB * 256 + d];
    int t0 = tc * 64;
    float xm1 = (t0 >= 1) ? __half2float(px[(t0 - 1) * 512]) : 0.0f;
    float xm2 = (t0 >= 2) ? __half2float(px[(t0 - 2) * 512]) : 0.0f;
    float xm3 = (t0 >= 3) ? __half2float(px[(t0 - 3) * 512]) : 0.0f;
    for (int q4 = 0; q4 < 16; q4++) {
        float xv[4];
#pragma unroll
        for (int j = 0; j < 4; j++) xv[j] = __half2float(px[(t0 + q4 * 4 + j) * 512]);
#pragma unroll
        for (int j = 0; j < 4; j++) {
            float x = xv[j];
            float acc = fmaf(x, w3, fmaf(xm1, w2, fmaf(xm2, w1, fmaf(xm3, w0, bias))));
            pxs[(t0 + q4 * 4 + j) * 256] = __float2half_rn(siluf(acc));
            xm3 = xm2; xm2 = xm1; xm1 = x;
        }
    }
}

// ---------------------------------------------------------------------------
// K3: x_proj fp16 GEMM.  128x64 tile, K=256 (4 stages of 64). cols<40 valid.
// ---------------------------------------------------------------------------
#define XP_A_H (128 * 72)
#define XP_B_H (64 * 72)
__global__ void __launch_bounds__(256, 2) k_gemm_xp() {
    extern __shared__ __half hsm[];
    __half* Asm = hsm;
    __half* Bsm = hsm + 2 * XP_A_H;
    int tt = blockIdx.y;
    int ib = blockIdx.z;
    int i = ib >> 2;
    int T = scanT(i);
    if (tt * 128 >= T) return;
    int t0 = tt * 128;
    int SB = c_TB[ib];
    int tid = threadIdx.x;
    int warp = tid >> 5, lane = tid & 31;
    int wm = warp & 3, wn = warp >> 2;
    int lg = lane >> 2, lt = lane & 3;

    auto load_stage = [&](int st, int kc) {
#pragma unroll
        for (int p = 0; p < 4; p++) {
            int q = p * 256 + tid;
            int ch = q & 7, m = q >> 3;
            cpa16(&Asm[st * XP_A_H + m * 72 + ch * 8],
                  &g_XS[(SB + t0 + m) * 256 + kc * 64 + ch * 8]);
        }
#pragma unroll
        for (int p = 0; p < 2; p++) {
            int q = p * 256 + tid;
            int ch = q & 7, n = q >> 3;
            cpa16(&Bsm[st * XP_B_H + n * 72 + ch * 8],
                  &g_WTxpH[(i * 64 + n) * 256 + kc * 64 + ch * 8]);
        }
    };

    float c[2][4][4] = {};
    load_stage(0, 0); CP_COMMIT();
    for (int kc = 0; kc < 4; kc++) {
        if (kc + 1 < 4) { load_stage((kc + 1) & 1, kc + 1); CP_COMMIT(); CP_WAIT1(); }
        else CP_WAIT0();
        __syncthreads();
        const __half* Ab = &Asm[(kc & 1) * XP_A_H];
        const __half* Bb = &Bsm[(kc & 1) * XP_B_H];
#pragma unroll
        for (int j = 0; j < 4; j++) {
            int kb = j * 16 + 2 * lt;
            uint32_t a[2][4];
#pragma unroll
            for (int mt = 0; mt < 2; mt++) {
                int mr = wm * 32 + mt * 16 + lg;
                a[mt][0] = ldh2(&Ab[mr * 72 + kb]);
                a[mt][1] = ldh2(&Ab[(mr + 8) * 72 + kb]);
                a[mt][2] = ldh2(&Ab[mr * 72 + kb + 8]);
                a[mt][3] = ldh2(&Ab[(mr + 8) * 72 + kb + 8]);
            }
            uint32_t bb[4][2];
#pragma unroll
            for (int n4 = 0; n4 < 4; n4++) {
                int nb = wn * 32 + n4 * 8 + lg;
                bb[n4][0] = ldh2(&Bb[nb * 72 + kb]);
                bb[n4][1] = ldh2(&Bb[nb * 72 + kb + 8]);
            }
#pragma unroll
            for (int mt = 0; mt < 2; mt++)
#pragma unroll
                for (int n4 = 0; n4 < 4; n4++)
                    MMA_F16(c[mt][n4], a[mt], bb[n4]);
        }
        __syncthreads();
    }
#pragma unroll
    for (int mt = 0; mt < 2; mt++)
#pragma unroll
        for (int n4 = 0; n4 < 4; n4++) {
            int row = t0 + wm * 32 + mt * 16 + lg;
            int col = wn * 32 + n4 * 8 + 2 * lt;
            if (col < 40) {
                *(float2*)&g_XDBL[(SB + row) * 40 + col]     = make_float2(c[mt][n4][0], c[mt][n4][1]);
                *(float2*)&g_XDBL[(SB + row + 8) * 40 + col] = make_float2(c[mt][n4][2], c[mt][n4][3]);
            }
        }
}

// ---------------------------------------------------------------------------
// K5a: chunk-local scan (delta fused inline). thread=d.
// ---------------------------------------------------------------------------
__global__ void k_scan1(const float* __restrict__ alog,
                        const float* __restrict__ dtw, const float* __restrict__ dtb) {
    int c = blockIdx.x, ib = blockIdx.y;
    int i = ib >> 2;
    int T = scanT(i);
    int LC = T / NCHUNK;
    int d = threadIdx.x;
    int SB = c_TB[ib];
    bool pw = (g_powBad == 0);
    float A0 = -__expf(alog[(i * 256 + d) * 16]);
    float4 dw0 = *(const float4*)&dtw[(i * 256 + d) * 8];
    float4 dw1 = *(const float4*)&dtw[(i * 256 + d) * 8 + 4];
    float dbias = dtb[i * 256 + d];
    const __half* pU = &g_XS[SB * 256 + d];
    const float* pBC = &g_XDBL[SB * 40];
    float h[16];
#pragma unroll
    for (int s = 0; s < 16; s++) h[s] = 0.0f;
    float dsum = 0.0f;
    int t0 = c * LC;
    if (pw) {
#pragma unroll 2
        for (int t = t0; t < t0 + LC; t++) {
            const float4* r = (const float4*)&pBC[t * 40];
            float4 a0 = r[0], a1 = r[1];
            float pre = dbias;
            pre = fmaf(a0.x, dw0.x, pre); pre = fmaf(a0.y, dw0.y, pre);
            pre = fmaf(a0.z, dw0.z, pre); pre = fmaf(a0.w, dw0.w, pre);
            pre = fmaf(a1.x, dw1.x, pre); pre = fmaf(a1.y, dw1.y, pre);
            pre = fmaf(a1.z, dw1.z, pre); pre = fmaf(a1.w, dw1.w, pre);
            float dv = softplusf(pre);
            float du = dv * __half2float(pU[t * 256]);
            dsum += dv;
            float q = __expf(dv * A0);
            float4 B0 = r[2], B1 = r[3], B2 = r[4], B3 = r[5];
            float ap = q;
            h[0]  = fmaf(ap, h[0],  du * B0.x); ap *= q;
            h[1]  = fmaf(ap, h[1],  du * B0.y); ap *= q;
            h[2]  = fmaf(ap, h[2],  du * B0.z); ap *= q;
            h[3]  = fmaf(ap, h[3],  du * B0.w); ap *= q;
            h[4]  = fmaf(ap, h[4],  du * B1.x); ap *= q;
            h[5]  = fmaf(ap, h[5],  du * B1.y); ap *= q;
            h[6]  = fmaf(ap, h[6],  du * B1.z); ap *= q;
            h[7]  = fmaf(ap, h[7],  du * B1.w); ap *= q;
            h[8]  = fmaf(ap, h[8],  du * B2.x); ap *= q;
            h[9]  = fmaf(ap, h[9],  du * B2.y); ap *= q;
            h[10] = fmaf(ap, h[10], du * B2.z); ap *= q;
            h[11] = fmaf(ap, h[11], du * B2.w); ap *= q;
            h[12] = fmaf(ap, h[12], du * B3.x); ap *= q;
            h[13] = fmaf(ap, h[13], du * B3.y); ap *= q;
            h[14] = fmaf(ap, h[14], du * B3.z); ap *= q;
            h[15] = fmaf(ap, h[15], du * B3.w);
        }
    } else {
        float As[16];
#pragma unroll
        for (int s = 0; s < 16; s++) As[s] = -__expf(alog[(i * 256 + d) * 16 + s]);
        for (int t = t0; t < t0 + LC; t++) {
            const float4* r = (const float4*)&pBC[t * 40];
            float4 a0 = r[0], a1 = r[1];
            float pre = dbias;
            pre = fmaf(a0.x, dw0.x, pre); pre = fmaf(a0.y, dw0.y, pre);
            pre = fmaf(a0.z, dw0.z, pre); pre = fmaf(a0.w, dw0.w, pre);
            pre = fmaf(a1.x, dw1.x, pre); pre = fmaf(a1.y, dw1.y, pre);
            pre = fmaf(a1.z, dw1.z, pre); pre = fmaf(a1.w, dw1.w, pre);
            float dv = softplusf(pre);
            float du = dv * __half2float(pU[t * 256]);
            dsum += dv;
            const float* Bp = &pBC[t * 40 + 8];
#pragma unroll
            for (int s = 0; s < 16; s++) {
                float a = __expf(dv * As[s]);
                h[s] = fmaf(a, h[s], du * Bp[s]);
            }
        }
    }
    int base = ((ib * NCHUNK + c) * 256 + d) * 16;
#pragma unroll
    for (int s = 0; s < 16; s++) {
        float Ascale = pw ? (A0 * (float)(s + 1))
                          : (-__expf(alog[(i * 256 + d) * 16 + s]));
        g_CP[base + s] = __expf(Ascale * dsum);
        g_CH[base + s] = h[s];
    }
}

// ---------------------------------------------------------------------------
// K5b: prefix over chunks
// ---------------------------------------------------------------------------
__global__ void k_scan2() {
    int g = blockIdx.x * 256 + threadIdx.x;
    int ib = g >> 12;
    int rem = g & 4095;
    float hi = 0.0f;
    for (int c = 0; c < NCHUNK; c++) {
        int idx = ib * (NCHUNK * 4096) + c * 4096 + rem;
        g_HI[idx] = hi;
        hi = fmaf(g_CP[idx], hi, g_CH[idx]);
    }
}

// ---------------------------------------------------------------------------
// K5c: chunk recompute with true h_init; y -> YT (fp16) token-major.
// ---------------------------------------------------------------------------
__global__ void k_scan3(const float* __restrict__ alog, const float* __restrict__ Dv,
                        const float* __restrict__ dtw, const float* __restrict__ dtb) {
    int c = blockIdx.x, ib = blockIdx.y;
    int i = ib >> 2;
    int T = scanT(i);
    int LC = T / NCHUNK;
    int d = threadIdx.x;
    int SB = c_TB[ib];
    bool pw = (g_powBad == 0);
    float A0 = -__expf(alog[(i * 256 + d) * 16]);
    float Dreg = Dv[i * 256 + d];
    float4 dw0 = *(const float4*)&dtw[(i * 256 + d) * 8];
    float4 dw1 = *(const float4*)&dtw[(i * 256 + d) * 8 + 4];
    float dbias = dtb[i * 256 + d];
    const __half* pU = &g_XS[SB * 256 + d];
    const __half* pZ = &g_XZ[SB * 512 + 256 + d];
    const float* pBC = &g_XDBL[SB * 40];
    __half* pY = &g_YT[SB * 256 + d];
    float h[16];
    {
        int base = ((ib * NCHUNK + c) * 256 + d) * 16;
#pragma unroll
        for (int s = 0; s < 16; s++) h[s] = g_HI[base + s];
    }
    int t0 = c * LC;
    if (pw) {
#pragma unroll 2
        for (int t = t0; t < t0 + LC; t++) {
            const float4* r = (const float4*)&pBC[t * 40];
            float4 a0 = r[0], a1 = r[1];
            float pre = dbias;
            pre = fmaf(a0.x, dw0.x, pre); pre = fmaf(a0.y, dw0.y, pre);
            pre = fmaf(a0.z, dw0.z, pre); pre = fmaf(a0.w, dw0.w, pre);
            pre = fmaf(a1.x, dw1.x, pre); pre = fmaf(a1.y, dw1.y, pre);
            pre = fmaf(a1.z, dw1.z, pre); pre = fmaf(a1.w, dw1.w, pre);
            float dv = softplusf(pre);
            float u = __half2float(pU[t * 256]);
            float du = dv * u;
            float q = __expf(dv * A0);
            float4 B0 = r[2], B1 = r[3], B2 = r[4], B3 = r[5];
            float4 C0 = r[6], C1 = r[7], C2 = r[8], C3 = r[9];
            float ys = 0.0f;
            float ap = q;
            h[0]  = fmaf(ap, h[0],  du * B0.x); ys = fmaf(h[0],  C0.x, ys); ap *= q;
            h[1]  = fmaf(ap, h[1],  du * B0.y); ys = fmaf(h[1],  C0.y, ys); ap *= q;
            h[2]  = fmaf(ap, h[2],  du * B0.z); ys = fmaf(h[2],  C0.z, ys); ap *= q;
            h[3]  = fmaf(ap, h[3],  du * B0.w); ys = fmaf(h[3],  C0.w, ys); ap *= q;
            h[4]  = fmaf(ap, h[4],  du * B1.x); ys = fmaf(h[4],  C1.x, ys); ap *= q;
            h[5]  = fmaf(ap, h[5],  du * B1.y); ys = fmaf(h[5],  C1.y, ys); ap *= q;
            h[6]  = fmaf(ap, h[6],  du * B1.z); ys = fmaf(h[6],  C1.z, ys); ap *= q;
            h[7]  = fmaf(ap, h[7],  du * B1.w); ys = fmaf(h[7],  C1.w, ys); ap *= q;
            h[8]  = fmaf(ap, h[8],  du * B2.x); ys = fmaf(h[8],  C2.x, ys); ap *= q;
            h[9]  = fmaf(ap, h[9],  du * B2.y); ys = fmaf(h[9],  C2.y, ys); ap *= q;
            h[10] = fmaf(ap, h[10], du * B2.z); ys = fmaf(h[10], C2.z, ys); ap *= q;
            h[11] = fmaf(ap, h[11], du * B2.w); ys = fmaf(h[11], C2.w, ys); ap *= q;
            h[12] = fmaf(ap, h[12], du * B3.x); ys = fmaf(h[12], C3.x, ys); ap *= q;
            h[13] = fmaf(ap, h[13], du * B3.y); ys = fmaf(h[13], C3.y, ys); ap *= q;
            h[14] = fmaf(ap, h[14], du * B3.z); ys = fmaf(h[14], C3.z, ys); ap *= q;
            h[15] = fmaf(ap, h[15], du * B3.w); ys = fmaf(h[15], C3.w, ys);
            float z = __half2float(pZ[t * 512]);
            pY[t * 256] = __float2half_rn(fmaf(u, Dreg, ys) * z);
        }
    } else {
        float As[16];
#pragma unroll
        for (int s = 0; s < 16; s++) As[s] = -__expf(alog[(i * 256 + d) * 16 + s]);
        for (int t = t0; t < t0 + LC; t++) {
            const float4* r = (const float4*)&pBC[t * 40];
            float4 a0 = r[0], a1 = r[1];
            float pre = dbias;
            pre = fmaf(a0.x, dw0.x, pre); pre = fmaf(a0.y, dw0.y, pre);
            pre = fmaf(a0.z, dw0.z, pre); pre = fmaf(a0.w, dw0.w, pre);
            pre = fmaf(a1.x, dw1.x, pre); pre = fmaf(a1.y, dw1.y, pre);
            pre = fmaf(a1.z, dw1.z, pre); pre = fmaf(a1.w, dw1.w, pre);
            float dv = softplusf(pre);
            float u = __half2float(pU[t * 256]);
            float du = dv * u;
            const float* Bp = &pBC[t * 40 + 8];
            float ys = 0.0f;
#pragma unroll
            for (int s = 0; s < 16; s++) {
                float a = __expf(dv * As[s]);
                h[s] = fmaf(a, h[s], du * Bp[s]);
                ys = fmaf(h[s], Bp[16 + s], ys);
            }
            float z = __half2float(pZ[t * 512]);
            pY[t * 256] = __float2half_rn(fmaf(u, Dreg, ys) * z);
        }
    }
}

// ---------------------------------------------------------------------------
// K6: out_proj fp16 GEMM.  128x128 tile, K=256 (4 stages of 64).
// ---------------------------------------------------------------------------
__global__ void __launch_bounds__(256, 2) k_gemm_out() {
    extern __shared__ __half hsm[];
    __half* Asm = hsm;
    __half* Bsm = hsm + 2 * IN_A_H;
    int tt = blockIdx.y;
    int ib = blockIdx.z;
    int i = ib >> 2;
    int T = scanT(i);
    if (tt * 128 >= T) return;
    int t0 = tt * 128;
    int SB = c_TB[ib];
    int tid = threadIdx.x;
    int warp = tid >> 5, lane = tid & 31;
    int wm = warp & 3, wn = warp >> 2;
    int lg = lane >> 2, lt = lane & 3;

    auto load_stage = [&](int st, int kc) {
#pragma unroll
        for (int p = 0; p < 4; p++) {
            int q = p * 256 + tid;
            int ch = q & 7, m = q >> 3;
            cpa16(&Asm[st * IN_A_H + m * 72 + ch * 8],
                  &g_YT[(SB + t0 + m) * 256 + kc * 64 + ch * 8]);
        }
#pragma unroll
        for (int p = 0; p < 4; p++) {
            int q = p * 256 + tid;
            int ch = q & 7, n = q >> 3;
            cpa16(&Bsm[st * IN_B_H + n * 72 + ch * 8],
                  &g_WToutH[(i * 128 + n) * 256 + kc * 64 + ch * 8]);
        }
    };

    float c[2][8][4] = {};
    load_stage(0, 0); CP_COMMIT();
    for (int kc = 0; kc < 4; kc++) {
        if (kc + 1 < 4) { load_stage((kc + 1) & 1, kc + 1); CP_COMMIT(); CP_WAIT1(); }
        else CP_WAIT0();
        __syncthreads();
        const __half* Ab = &Asm[(kc & 1) * IN_A_H];
        const __half* Bb = &Bsm[(kc & 1) * IN_B_H];
#pragma unroll
        for (int j = 0; j < 4; j++) {
            int kb = j * 16 + 2 * lt;
            uint32_t a[2][4];
#pragma unroll
            for (int mt = 0; mt < 2; mt++) {
                int mr = wm * 32 + mt * 16 + lg;
                a[mt][0] = ldh2(&Ab[mr * 72 + kb]);
                a[mt][1] = ldh2(&Ab[(mr + 8) * 72 + kb]);
                a[mt][2] = ldh2(&Ab[mr * 72 + kb + 8]);
                a[mt][3] = ldh2(&Ab[(mr + 8) * 72 + kb + 8]);
            }
            uint32_t bb[8][2];
#pragma unroll
            for (int n4 = 0; n4 < 8; n4++) {
                int nb = wn * 64 + n4 * 8 + lg;
                bb[n4][0] = ldh2(&Bb[nb * 72 + kb]);
                bb[n4][1] = ldh2(&Bb[nb * 72 + kb + 8]);
            }
#pragma unroll
            for (int mt = 0; mt < 2; mt++)
#pragma unroll
                for (int n4 = 0; n4 < 8; n4++)
                    MMA_F16(c[mt][n4], a[mt], bb[n4]);
        }
        __syncthreads();
    }
#pragma unroll
    for (int mt = 0; mt < 2; mt++)
#pragma unroll
        for (int n4 = 0; n4 < 8; n4++) {
            int row = t0 + wm * 32 + mt * 16 + lg;
            int col = wn * 64 + n4 * 8 + 2 * lt;
            *(float2*)&g_OUT[(SB + row) * 128 + col]     = make_float2(c[mt][n4][0], c[mt][n4][1]);
            *(float2*)&g_OUT[(SB + row + 8) * 128 + col] = make_float2(c[mt][n4][2], c[mt][n4][3]);
        }
}

// interp of backward-scan output
__device__ __forceinline__ float interp_flip(int i, int b, int l, int c) {
    float pos = 0.5f * (float)(8191 - l) - 0.25f;
    pos = fminf(fmaxf(pos, 0.0f), 4095.0f);
    int lo = (int)floorf(pos);
    int hi = min(lo + 1, 4095);
    float w = pos - (float)lo;
    const float* ob = &g_OUT[c_TB[i * 4 + b] * 128 + c];
    return ob[lo * 128] * (1.0f - w) + ob[hi * 128] * w;
}

// ---------------------------------------------------------------------------
// K7: merge 4 scan outputs -> a,b maps [2][B][C][64][64]
// ---------------------------------------------------------------------------
__global__ void k_merge() {
    __shared__ float S[64][129];
    int irow = blockIdx.x;
    int b = blockIdx.y;
    int tid = threadIdx.x;
    for (int half_ = 0; half_ < 2; half_++) {
        for (int p = 0; p < 32; p++) {
            int idx = p * 256 + tid;
            int c = idx & 127, j = idx >> 7;
            int l  = irow * 128 + j + (half_ ? 64 : 0);
            int l2 = j * 128 + irow + (half_ ? 64 : 0);
            float v = g_OUT[(c_TB[b] + l) * 128 + c];
            v += interp_flip(1, b, l, c);
            v += g_OUT[(c_TB[8 + b] + l2) * 128 + c];
            v += interp_flip(3, b, l2, c);
            S[j][c] = v;
        }
        __syncthreads();
        for (int p = 0; p < 32; p++) {
            int idx = p * 256 + tid;
            int j = idx & 63, c = idx >> 6;
            g_AB[((half_ * 4 + b) * 128 + c) * 4096 + irow * 64 + j] = S[j][c];
        }
        __syncthreads();
    }
}

// ---------------------------------------------------------------------------
// K8: bilinear 64->128 upsample + residuals
// ---------------------------------------------------------------------------
__global__ void k_final(const float* __restrict__ fa, const float* __restrict__ fb,
                        float* __restrict__ out) {
    int idx = blockIdx.x * 256 + threadIdx.x;
    int w = idx & 127, hh = (idx >> 7) & 127, c = (idx >> 14) & 127, b = idx >> 21;
    float ph = fminf(fmaxf(0.5f * hh - 0.25f, 0.0f), 63.0f);
    int h0 = (int)floorf(ph); int h1 = min(h0 + 1, 63); float wh = ph - (float)h0;
    float pw = fminf(fmaxf(0.5f * w - 0.25f, 0.0f), 63.0f);
    int w0 = (int)floorf(pw); int w1 = min(w0 + 1, 63); float ww = pw - (float)w0;
    const float* Aa = &g_AB[((0 * 4 + b) * 128 + c) * 4096];
    const float* Bb = &g_AB[((1 * 4 + b) * 128 + c) * 4096];
    float av = (Aa[h0 * 64 + w0] * (1.0f - ww) + Aa[h0 * 64 + w1] * ww) * (1.0f - wh)
             + (Aa[h1 * 64 + w0] * (1.0f - ww) + Aa[h1 * 64 + w1] * ww) * wh;
    float bv = (Bb[h0 * 64 + w0] * (1.0f - ww) + Bb[h0 * 64 + w1] * ww) * (1.0f - wh)
             + (Bb[h1 * 64 + w0] * (1.0f - ww) + Bb[h1 * 64 + w1] * ww) * wh;
    out[idx] = av + bv + fa[idx] + fb[idx];
}

// ---------------------------------------------------------------------------
extern "C" void kernel_launch(void* const* d_in, const int* in_sizes, int n_in,
                              void* d_out, int out_size) {
    (void)in_sizes; (void)n_in; (void)out_size;
    const float* fa   = (const float*)d_in[0];
    const float* fb   = (const float*)d_in[1];
    const float* inw  = (const float*)d_in[2];
    const float* cw   = (const float*)d_in[3];
    const float* cb   = (const float*)d_in[4];
    const float* xpw  = (const float*)d_in[5];
    const float* dtw  = (const float*)d_in[6];
    const float* dtb  = (const float*)d_in[7];
    const float* alog = (const float*)d_in[8];
    const float* Dv   = (const float*)d_in[9];
    const float* outw = (const float*)d_in[10];
    float* out = (float*)d_out;

    const int SMEM_IN = 2 * (IN_A_H + IN_B_H) * 2;   // 73728 B
    const int SMEM_XP = 2 * (XP_A_H + XP_B_H) * 2;   // 55296 B
    cudaFuncSetAttribute(k_gemm_in,  cudaFuncAttributeMaxDynamicSharedMemorySize, SMEM_IN);
    cudaFuncSetAttribute(k_gemm_xp,  cudaFuncAttributeMaxDynamicSharedMemorySize, SMEM_XP);
    cudaFuncSetAttribute(k_gemm_out, cudaFuncAttributeMaxDynamicSharedMemorySize, SMEM_IN);

    k_gather<<<dim3(2, 64, 4), 256>>>(fa, fb);
    k_prep_w<<<1024, 256>>>(inw, xpw, outw);
    k_prep_chk<<<64, 256>>>(alog);
    k_gemm_in<<<dim3(4, 64, 16), 256, SMEM_IN>>>();
    k_conv<<<dim3(128, 16), 256>>>(cw, cb);
    k_gemm_xp<<<dim3(1, 64, 16), 256, SMEM_XP>>>();
    k_scan1<<<dim3(NCHUNK, 16), 256>>>(alog, dtw, dtb);
    k_scan2<<<256, 256>>>();
    k_scan3<<<dim3(NCHUNK, 16), 256>>>(alog, Dv, dtw, dtb);
    k_gemm_out<<<dim3(1, 64, 16), 256, SMEM_IN>>>();
    k_merge<<<dim3(64, 4), 256>>>();
    k_final<<<32768, 256>>>(fa, fb, out);
}